// round 4
// baseline (speedup 1.0000x reference)
#include <cuda_runtime.h>
#include <cuda_fp16.h>
#include <cstdint>

// Problem constants
#define NROWS 10000
#define KDIM  10000
#define F     20      // hidden width
#define D     128     // in/out width
#define BK    200     // k-chunk for the big GEMM staging
#define KSTEPS (BK/8) // 25 mma k-steps per chunk
#define NSTRIPS ((NROWS + 15) / 16)   // 625 (exact)
#define TS_PAD 32     // pad so n-tile over-read (cols 20..23) stays in bounds

// K-split for occupancy: 10 slabs of 1000 columns each
#define SPLIT  10
#define SLAB   (KDIM / SPLIT)   // 1000
#define CHUNKS (SLAB / BK)      // 5
#define STRIPS_PER_BLK 8
#define NSTRIP_GROUPS ((NSTRIPS + STRIPS_PER_BLK - 1) / STRIPS_PER_BLK)  // 79
#define PF 5          // A-load pipeline depth (divides KSTEPS)

// Scratch (no allocations allowed)
__device__ float  g_bufT[NROWS * F];
__device__ float  g_bufH[NROWS * F];
__device__ float  g_part[SPLIT * NROWS * F];      // 8 MB partials
__device__ __half g_adjh[(size_t)NROWS * KDIM];   // 200 MB fp16 adj copy

__device__ __forceinline__ uint32_t f2tf(float f) {
    uint32_t u;
    asm("cvt.rna.tf32.f32 %0, %1;" : "=r"(u) : "f"(f));
    return u;
}

// ---------------------------------------------------------------------------
// Big GEMM partial: part[slab][N,20] = adj[:, slab] @ T[slab, 20]
// PASS 0: reads fp32 adj, ALSO writes fp16 copy to g_adjh.
// PASS 1: reads fp16 g_adjh (same 10-bit mantissa as tf32 -> no extra error).
// Per-warp 16-row strip over one k-slab; 8 warps/block share B staging.
// k-within-8 permuted (frag col c <-> k = 2*(c&3) + (c>>2)): A loads are
// contiguous per lane, B smem reads at stride 20 are conflict-free.
// A loads run through a PF-deep register ring carried across chunk syncs.
// ---------------------------------------------------------------------------
template <int PASS>
__global__ void __launch_bounds__(256)
spmm_part_kernel(const float* __restrict__ adj,
                 const float* __restrict__ T,
                 float* __restrict__ part)
{
    __shared__ uint32_t Ts[BK * F + TS_PAD];  // tf32 bits, natural stride 20

    const int tid  = threadIdx.x;
    const int warp = tid >> 5;
    const int lane = tid & 31;
    const int gid  = lane >> 2;   // 0..7  (row-in-group)
    const int tig  = lane & 3;    // 0..3  (k selector)
    const int tig2 = 2 * tig;

    if (tid < TS_PAD) Ts[BK * F + tid] = 0;   // benign pad for n-tile overhang

    const int strip  = blockIdx.x * STRIPS_PER_BLK + warp;
    const bool active = (strip < NSTRIPS);
    const int m0   = strip * 16;
    const int slab = blockIdx.y;
    const int rbase = active ? (m0 + gid) : 0;

    const float*  a_row0  = adj    + (size_t)rbase * KDIM + (size_t)slab * SLAB;
    const float*  a_row1  = a_row0 + (size_t)8 * KDIM;
    __half*       ah_row0 = g_adjh + (size_t)rbase * KDIM + (size_t)slab * SLAB;
    __half*       ah_row1 = ah_row0 + (size_t)8 * KDIM;

    float acc[3][4];
#pragma unroll
    for (int t = 0; t < 3; t++)
#pragma unroll
        for (int j = 0; j < 4; j++) acc[t][j] = 0.0f;

    // A-load register ring (PF ksteps deep)
    float2  ra[PF], rb[PF];
    __half2 ha[PF], hb[PF];
#pragma unroll
    for (int p = 0; p < PF; p++) {
        const int off = p * 8 + tig2;
        if (PASS == 0) {
            ra[p] = *(const float2*)(a_row0 + off);
            rb[p] = *(const float2*)(a_row1 + off);
        } else {
            ha[p] = *(const __half2*)(ah_row0 + off);
            hb[p] = *(const __half2*)(ah_row1 + off);
        }
    }

    for (int ch = 0; ch < CHUNKS; ++ch) {
        __syncthreads();   // previous chunk's LDS done before overwrite
        {
            // stage B chunk (BK*20 = 4000 floats, contiguous) as tf32
            const float4* src =
                (const float4*)(T + ((size_t)slab * SLAB + (size_t)ch * BK) * F);
            uint4* dst = (uint4*)Ts;
#pragma unroll
            for (int it = 0; it < (BK * F) / 4 / 256 + 1; ++it) {
                int i = it * 256 + tid;
                if (i < (BK * F) / 4) {
                    float4 v = src[i];
                    uint4 u;
                    u.x = f2tf(v.x); u.y = f2tf(v.y);
                    u.z = f2tf(v.z); u.w = f2tf(v.w);
                    dst[i] = u;
                }
            }
        }
        __syncthreads();

        if (active) {
            const int chbase = ch * BK;
#pragma unroll
            for (int ks = 0; ks < KSTEPS; ++ks) {
                const int slot = ks % PF;       // compile-time (PF | KSTEPS)

                // ---- consume current kstep from ring ----
                float2 va, vb;
                if (PASS == 0) {
                    va = ra[slot]; vb = rb[slot];
                    // write-through fp16 copy (each element exactly once)
                    const int off = chbase + ks * 8 + tig2;
                    *(__half2*)(ah_row0 + off) = __floats2half2_rn(va.x, va.y);
                    *(__half2*)(ah_row1 + off) = __floats2half2_rn(vb.x, vb.y);
                } else {
                    va = __half22float2(ha[slot]);
                    vb = __half22float2(hb[slot]);
                }

                uint32_t a0, a1, a2, a3;
                if (PASS == 0) {
                    a0 = f2tf(va.x); a2 = f2tf(va.y);
                    a1 = f2tf(vb.x); a3 = f2tf(vb.y);
                } else {
                    // fp16 values are exact in tf32 -> reinterpret suffices
                    a0 = __float_as_uint(va.x); a2 = __float_as_uint(va.y);
                    a1 = __float_as_uint(vb.x); a3 = __float_as_uint(vb.y);
                }

                // ---- prefetch kstep (global) + PF into ring ----
                {
                    const int nko = chbase + (ks + PF) * 8 + tig2;
                    const bool v = (nko < SLAB);
                    const int  po = v ? nko : tig2;
                    if (PASS == 0) {
                        ra[slot] = *(const float2*)(a_row0 + po);
                        rb[slot] = *(const float2*)(a_row1 + po);
                    } else {
                        ha[slot] = *(const __half2*)(ah_row0 + po);
                        hb[slot] = *(const __half2*)(ah_row1 + po);
                    }
                }

                const int bs0 = (ks * 8 + tig2)     * F;  // frag row tig
                const int bs1 = (ks * 8 + tig2 + 1) * F;  // frag row tig+4
#pragma unroll
                for (int t = 0; t < 3; t++) {
                    uint32_t b0 = Ts[bs0 + 8 * t + gid];
                    uint32_t b1 = Ts[bs1 + 8 * t + gid];
                    asm volatile(
                        "mma.sync.aligned.m16n8k8.row.col.f32.tf32.tf32.f32 "
                        "{%0,%1,%2,%3},{%4,%5,%6,%7},{%8,%9},{%0,%1,%2,%3};"
                        : "+f"(acc[t][0]), "+f"(acc[t][1]),
                          "+f"(acc[t][2]), "+f"(acc[t][3])
                        : "r"(a0), "r"(a1), "r"(a2), "r"(a3),
                          "r"(b0), "r"(b1));
                }
            }
        }
    }

    if (active) {
        float* po = g_part + (size_t)slab * NROWS * F;
#pragma unroll
        for (int t = 0; t < 3; t++) {
            const int c = 8 * t + tig2;   // col pairs never straddle 20
            if (c < F) {
                const int r0 = m0 + gid;
                const int r1 = r0 + 8;
                *(float2*)(po + (size_t)r0 * F + c) =
                    make_float2(acc[t][0], acc[t][1]);
                *(float2*)(po + (size_t)r1 * F + c) =
                    make_float2(acc[t][2], acc[t][3]);
            }
        }
    }
    (void)part;
}

// ---------------------------------------------------------------------------
// Reduce partials: out[i] = relu( sum_s part[s][i] + bias[i%20] )
// ---------------------------------------------------------------------------
__global__ void __launch_bounds__(256)
reduce_kernel(const float* __restrict__ part, const float* __restrict__ bias,
              float* __restrict__ out)
{
    const int i = blockIdx.x * 256 + threadIdx.x;
    if (i < NROWS * F) {
        float s = 0.f;
#pragma unroll
        for (int sl = 0; sl < SPLIT; sl++)
            s += part[(size_t)sl * NROWS * F + i];
        out[i] = fmaxf(s + bias[i % F], 0.f);
    }
}

// ---------------------------------------------------------------------------
// Small GEMM: T[N,20] = Hin[N,KK] @ W[KK,20].  Warp per row, lane = out col.
// ---------------------------------------------------------------------------
template <int KK>
__global__ void __launch_bounds__(256)
xw_kernel(const float* __restrict__ Hin, const float* __restrict__ W,
          float* __restrict__ T)
{
    __shared__ float Ws[KK * F];
    const int tid = threadIdx.x;
    for (int i = tid; i < KK * F; i += 256) Ws[i] = W[i];
    __syncthreads();

    const int warp = tid >> 5;
    const int lane = tid & 31;
    const int row  = blockIdx.x * 8 + warp;   // grid*8 == NROWS exactly

    const float* h = Hin + (size_t)row * KK;
    if (lane < F) {
        float a0 = 0.f, a1 = 0.f, a2 = 0.f, a3 = 0.f;
#pragma unroll 4
        for (int k = 0; k < KK; k += 4) {
            a0 += h[k + 0] * Ws[(k + 0) * F + lane];
            a1 += h[k + 1] * Ws[(k + 1) * F + lane];
            a2 += h[k + 2] * Ws[(k + 2) * F + lane];
            a3 += h[k + 3] * Ws[(k + 3) * F + lane];
        }
        T[(size_t)row * F + lane] = (a0 + a1) + (a2 + a3);
    }
}

// ---------------------------------------------------------------------------
// Final (fused partial-reduce): out = relu( relu((sum_s P_s) @ W3 + b3) + x )
// ---------------------------------------------------------------------------
__global__ void __launch_bounds__(256)
final_kernel(const float* __restrict__ P, const float* __restrict__ W3,
             const float* __restrict__ b3, const float* __restrict__ x,
             float* __restrict__ out)
{
    __shared__ float Ws[F * D];    // 20 x 128
    __shared__ float ps[2 * F];    // reduced P rows for this block
    const int tid = threadIdx.x;
    for (int i = tid; i < F * D; i += 256) Ws[i] = W3[i];

    const int row0 = blockIdx.x * 2;
    if (tid < 2 * F) {
        const int r = tid / F, c = tid % F;
        float s = 0.f;
#pragma unroll
        for (int sl = 0; sl < SPLIT; sl++)
            s += P[(size_t)sl * NROWS * F + (size_t)(row0 + r) * F + c];
        ps[tid] = s;
    }
    __syncthreads();

    const int r   = tid >> 7;
    const int col = tid & 127;

    float acc = b3[col];
#pragma unroll
    for (int k = 0; k < F; k++) acc += ps[r * F + k] * Ws[k * D + col];

    const float h = fmaxf(acc, 0.f);
    const size_t o = (size_t)(row0 + r) * D + col;
    out[o] = fmaxf(h + x[o], 0.f);
}

// ---------------------------------------------------------------------------
extern "C" void kernel_launch(void* const* d_in, const int* in_sizes, int n_in,
                              void* d_out, int out_size)
{
    const float* x   = (const float*)d_in[0];
    const float* adj = (const float*)d_in[1];
    const float* W1  = (const float*)d_in[2];
    const float* b1  = (const float*)d_in[3];
    const float* W2  = (const float*)d_in[4];
    const float* b2  = (const float*)d_in[5];
    const float* W3  = (const float*)d_in[6];
    const float* b3  = (const float*)d_in[7];
    float* out = (float*)d_out;

    float *T, *H, *P;
    cudaGetSymbolAddress((void**)&T, g_bufT);
    cudaGetSymbolAddress((void**)&H, g_bufH);
    cudaGetSymbolAddress((void**)&P, g_part);

    const dim3 SPMM_GRID(NSTRIP_GROUPS, SPLIT);      // 79 x 10 blocks, 256 thr
    const int  RED_GRID = (NROWS * F + 255) / 256;   // 782

    // T1 = x @ W1
    xw_kernel<D><<<NROWS / 8, 256>>>(x, W1, T);
    // P = partials of adj @ T1   (pass 0: fp32 adj read + fp16 write-through)
    spmm_part_kernel<0><<<SPMM_GRID, 256>>>(adj, T, P);
    reduce_kernel<<<RED_GRID, 256>>>(P, b1, H);      // H1 = relu(. + b1)
    // T2 = H1 @ W2
    xw_kernel<F><<<NROWS / 8, 256>>>(H, W2, T);
    // P = partials of adj @ T2   (pass 1: fp16 adj)
    spmm_part_kernel<1><<<SPMM_GRID, 256>>>(adj, T, P);
    reduce_kernel<<<RED_GRID, 256>>>(P, b2, H);      // H2 = relu(. + b2)
    // P = partials of adj @ H2   (pass 1: fp16 adj)
    spmm_part_kernel<1><<<SPMM_GRID, 256>>>(adj, H, P);
    // out = relu(relu(sum(P) @ W3 + b3) + x)
    final_kernel<<<NROWS / 2, 256>>>(P, W3, b3, x, out);
}

// round 5
// speedup vs baseline: 1.3963x; 1.3963x over previous
#include <cuda_runtime.h>
#include <cstdint>

// Problem constants
#define NROWS 10000
#define KDIM  10000
#define F     20      // hidden width
#define D     128     // in/out width
#define BK    200     // k-chunk for the big GEMM staging
#define KSTEPS (BK/8) // 25 mma k-steps per chunk
#define NSTRIPS ((NROWS + 15) / 16)   // 625 (exact)
#define TS_PAD 32     // pad so n-tile over-read (cols 20..23) stays in bounds

// K-split for occupancy: 10 slabs of 1000 columns each
#define SPLIT  10
#define SLAB   (KDIM / SPLIT)   // 1000
#define CHUNKS (SLAB / BK)      // 5
#define STRIPS_PER_BLK 8
#define NSTRIP_GROUPS ((NSTRIPS + STRIPS_PER_BLK - 1) / STRIPS_PER_BLK)  // 79
#define PF 5          // A-load pipeline depth (must divide KSTEPS)

// Scratch (no allocations allowed)
__device__ float g_bufT[NROWS * F];
__device__ float g_bufH[NROWS * F];
__device__ float g_part[SPLIT * NROWS * F];   // 8 MB partials

__device__ __forceinline__ uint32_t f2tf(float f) {
    uint32_t u;
    asm("cvt.rna.tf32.f32 %0, %1;" : "=r"(u) : "f"(f));
    return u;
}

// ---------------------------------------------------------------------------
// Big GEMM partial: part[slab][N,20] = adj[:, slab] @ T[slab, 20]
// Per-warp 16-row strip over one k-slab; 8 warps/block share B staging.
// k-within-8 permuted (frag col c <-> k = 2*(c&3) + (c>>2)): A loads are
// contiguous float2 per lane, B smem reads at stride 20 are conflict-free.
// A loads run through a PF-deep register ring carried across chunk syncs
// (chunks are contiguous in k within a slab, so prefetch addresses are valid).
// ---------------------------------------------------------------------------
__global__ void __launch_bounds__(256)
spmm_part_kernel(const float* __restrict__ adj,
                 const float* __restrict__ T,
                 float* __restrict__ part)
{
    __shared__ uint32_t Ts[BK * F + TS_PAD];  // tf32 bits, natural stride 20

    const int tid  = threadIdx.x;
    const int warp = tid >> 5;
    const int lane = tid & 31;
    const int gid  = lane >> 2;   // 0..7  (row-in-group)
    const int tig  = lane & 3;    // 0..3  (k selector)
    const int tig2 = 2 * tig;

    if (tid < TS_PAD) Ts[BK * F + tid] = 0;   // benign pad for n-tile overhang

    const int strip  = blockIdx.x * STRIPS_PER_BLK + warp;
    const bool active = (strip < NSTRIPS);
    const int m0   = strip * 16;
    const int slab = blockIdx.y;
    const int rbase = active ? (m0 + gid) : 0;

    const float* a_row0 = adj + (size_t)rbase * KDIM + (size_t)slab * SLAB;
    const float* a_row1 = a_row0 + (size_t)8 * KDIM;

    float acc[3][4];
#pragma unroll
    for (int t = 0; t < 3; t++)
#pragma unroll
        for (int j = 0; j < 4; j++) acc[t][j] = 0.0f;

    // A-load register ring (PF ksteps deep)
    float2 ra[PF], rb[PF];
#pragma unroll
    for (int p = 0; p < PF; p++) {
        const int off = p * 8 + tig2;
        ra[p] = *(const float2*)(a_row0 + off);
        rb[p] = *(const float2*)(a_row1 + off);
    }

    for (int ch = 0; ch < CHUNKS; ++ch) {
        __syncthreads();   // previous chunk's LDS done before overwrite
        {
            // stage B chunk (BK*20 = 4000 floats, contiguous) as tf32
            const float4* src =
                (const float4*)(T + ((size_t)slab * SLAB + (size_t)ch * BK) * F);
            uint4* dst = (uint4*)Ts;
#pragma unroll
            for (int it = 0; it < (BK * F) / 4 / 256 + 1; ++it) {
                int i = it * 256 + tid;
                if (i < (BK * F) / 4) {
                    float4 v = src[i];
                    uint4 u;
                    u.x = f2tf(v.x); u.y = f2tf(v.y);
                    u.z = f2tf(v.z); u.w = f2tf(v.w);
                    dst[i] = u;
                }
            }
        }
        __syncthreads();

        if (active) {
            const int chbase = ch * BK;
#pragma unroll
            for (int ks = 0; ks < KSTEPS; ++ks) {
                const int slot = ks % PF;       // compile-time (PF | KSTEPS)

                // ---- consume current kstep from ring ----
                const float2 va = ra[slot];
                const float2 vb = rb[slot];
                const uint32_t a0 = f2tf(va.x);   // frag col tig   (k=2tig)
                const uint32_t a2 = f2tf(va.y);   // frag col tig+4 (k=2tig+1)
                const uint32_t a1 = f2tf(vb.x);
                const uint32_t a3 = f2tf(vb.y);

                // ---- prefetch kstep + PF into the ring ----
                {
                    const int nko = chbase + (ks + PF) * 8 + tig2;
                    const int po  = (nko < SLAB) ? nko : tig2;  // tail dummy
                    ra[slot] = *(const float2*)(a_row0 + po);
                    rb[slot] = *(const float2*)(a_row1 + po);
                }

                const int bs0 = (ks * 8 + tig2)     * F;  // frag row tig
                const int bs1 = (ks * 8 + tig2 + 1) * F;  // frag row tig+4
#pragma unroll
                for (int t = 0; t < 3; t++) {
                    uint32_t b0 = Ts[bs0 + 8 * t + gid];
                    uint32_t b1 = Ts[bs1 + 8 * t + gid];
                    asm volatile(
                        "mma.sync.aligned.m16n8k8.row.col.f32.tf32.tf32.f32 "
                        "{%0,%1,%2,%3},{%4,%5,%6,%7},{%8,%9},{%0,%1,%2,%3};"
                        : "+f"(acc[t][0]), "+f"(acc[t][1]),
                          "+f"(acc[t][2]), "+f"(acc[t][3])
                        : "r"(a0), "r"(a1), "r"(a2), "r"(a3),
                          "r"(b0), "r"(b1));
                }
            }
        }
    }

    if (active) {
        float* po = part + (size_t)slab * NROWS * F;
#pragma unroll
        for (int t = 0; t < 3; t++) {
            const int c = 8 * t + tig2;   // col pairs never straddle 20
            if (c < F) {
                const int r0 = m0 + gid;
                const int r1 = r0 + 8;
                *(float2*)(po + (size_t)r0 * F + c) =
                    make_float2(acc[t][0], acc[t][1]);
                *(float2*)(po + (size_t)r1 * F + c) =
                    make_float2(acc[t][2], acc[t][3]);
            }
        }
    }
}

// ---------------------------------------------------------------------------
// Reduce partials: out[i] = relu( sum_s part[s][i] + bias[i%20] )
// ---------------------------------------------------------------------------
__global__ void __launch_bounds__(256)
reduce_kernel(const float* __restrict__ part, const float* __restrict__ bias,
              float* __restrict__ out)
{
    const int i = blockIdx.x * 256 + threadIdx.x;
    if (i < NROWS * F) {
        float s = 0.f;
#pragma unroll
        for (int sl = 0; sl < SPLIT; sl++)
            s += part[(size_t)sl * NROWS * F + i];
        out[i] = fmaxf(s + bias[i % F], 0.f);
    }
}

// ---------------------------------------------------------------------------
// Small GEMM: T[N,20] = Hin[N,KK] @ W[KK,20].  Warp per row, lane = out col.
// ---------------------------------------------------------------------------
template <int KK>
__global__ void __launch_bounds__(256)
xw_kernel(const float* __restrict__ Hin, const float* __restrict__ W,
          float* __restrict__ T)
{
    __shared__ float Ws[KK * F];
    const int tid = threadIdx.x;
    for (int i = tid; i < KK * F; i += 256) Ws[i] = W[i];
    __syncthreads();

    const int warp = tid >> 5;
    const int lane = tid & 31;
    const int row  = blockIdx.x * 8 + warp;   // grid*8 == NROWS exactly

    const float* h = Hin + (size_t)row * KK;
    if (lane < F) {
        float a0 = 0.f, a1 = 0.f, a2 = 0.f, a3 = 0.f;
#pragma unroll 4
        for (int k = 0; k < KK; k += 4) {
            a0 += h[k + 0] * Ws[(k + 0) * F + lane];
            a1 += h[k + 1] * Ws[(k + 1) * F + lane];
            a2 += h[k + 2] * Ws[(k + 2) * F + lane];
            a3 += h[k + 3] * Ws[(k + 3) * F + lane];
        }
        T[(size_t)row * F + lane] = (a0 + a1) + (a2 + a3);
    }
}

// ---------------------------------------------------------------------------
// Final (fused partial-reduce): out = relu( relu((sum_s P_s) @ W3 + b3) + x )
// ---------------------------------------------------------------------------
__global__ void __launch_bounds__(256)
final_kernel(const float* __restrict__ P, const float* __restrict__ W3,
             const float* __restrict__ b3, const float* __restrict__ x,
             float* __restrict__ out)
{
    __shared__ float Ws[F * D];    // 20 x 128
    __shared__ float ps[2 * F];    // reduced P rows for this block
    const int tid = threadIdx.x;
    for (int i = tid; i < F * D; i += 256) Ws[i] = W3[i];

    const int row0 = blockIdx.x * 2;
    if (tid < 2 * F) {
        const int r = tid / F, c = tid % F;
        float s = 0.f;
#pragma unroll
        for (int sl = 0; sl < SPLIT; sl++)
            s += P[(size_t)sl * NROWS * F + (size_t)(row0 + r) * F + c];
        ps[tid] = s;
    }
    __syncthreads();

    const int r   = tid >> 7;
    const int col = tid & 127;

    float acc = b3[col];
#pragma unroll
    for (int k = 0; k < F; k++) acc += ps[r * F + k] * Ws[k * D + col];

    const float h = fmaxf(acc, 0.f);
    const size_t o = (size_t)(row0 + r) * D + col;
    out[o] = fmaxf(h + x[o], 0.f);
}

// ---------------------------------------------------------------------------
extern "C" void kernel_launch(void* const* d_in, const int* in_sizes, int n_in,
                              void* d_out, int out_size)
{
    const float* x   = (const float*)d_in[0];
    const float* adj = (const float*)d_in[1];
    const float* W1  = (const float*)d_in[2];
    const float* b1  = (const float*)d_in[3];
    const float* W2  = (const float*)d_in[4];
    const float* b2  = (const float*)d_in[5];
    const float* W3  = (const float*)d_in[6];
    const float* b3  = (const float*)d_in[7];
    float* out = (float*)d_out;

    float *T, *H, *P;
    cudaGetSymbolAddress((void**)&T, g_bufT);
    cudaGetSymbolAddress((void**)&H, g_bufH);
    cudaGetSymbolAddress((void**)&P, g_part);

    const dim3 SPMM_GRID(NSTRIP_GROUPS, SPLIT);      // 79 x 10 blocks, 256 thr
    const int  RED_GRID = (NROWS * F + 255) / 256;   // 782

    // T1 = x @ W1
    xw_kernel<D><<<NROWS / 8, 256>>>(x, W1, T);
    // H1 = relu(adj @ T1 + b1)
    spmm_part_kernel<<<SPMM_GRID, 256>>>(adj, T, P);
    reduce_kernel<<<RED_GRID, 256>>>(P, b1, H);
    // T2 = H1 @ W2
    xw_kernel<F><<<NROWS / 8, 256>>>(H, W2, T);
    // H2 = relu(adj @ T2 + b2)
    spmm_part_kernel<<<SPMM_GRID, 256>>>(adj, T, P);
    reduce_kernel<<<RED_GRID, 256>>>(P, b2, H);
    // P = partials of adj @ H2
    spmm_part_kernel<<<SPMM_GRID, 256>>>(adj, H, P);
    // out = relu(relu(sum(P) @ W3 + b3) + x)
    final_kernel<<<NROWS / 2, 256>>>(P, W3, b3, x, out);
}

// round 6
// speedup vs baseline: 1.4222x; 1.0185x over previous
#include <cuda_runtime.h>
#include <cstdint>

// Problem constants
#define NROWS 10000
#define KDIM  10000
#define F     20      // hidden width
#define D     128     // in/out width
#define NSTRIPS ((NROWS + 15) / 16)   // 625 (exact)

// K-split: 25 slabs of 400 columns (16 | 400 -> integer wide-steps)
#define SPLIT  25
#define SLAB   400
#define WSTEPS (SLAB / 16)      // 25 wide steps (2 MMAs each)
#define STRIPS_PER_BLK 8
#define NSTRIP_GROUPS ((NSTRIPS + STRIPS_PER_BLK - 1) / STRIPS_PER_BLK)  // 79
#define PF 4                    // A-load ring depth (float4 pairs)

#define BSTRIDE 22              // B smem row stride in words (conflict-free)
#define TS_WORDS (SLAB * BSTRIDE + 32)

// Scratch (no allocations allowed)
__device__ float g_bufT[NROWS * F];
__device__ float g_bufH[NROWS * F];
__device__ float g_part[SPLIT * NROWS * F];   // 20 MB partials

__device__ __forceinline__ uint32_t f2tf(float f) {
    uint32_t u;
    asm("cvt.rna.tf32.f32 %0, %1;" : "=r"(u) : "f"(f));
    return u;
}

// ---------------------------------------------------------------------------
// Big GEMM partial: part[slab][N,20] = adj[:, slab] @ T[slab, 20]
// Per-warp 16-row strip over one 400-col k-slab; 8 warps/block share staging.
// Wide A loads: each lane loads float4 (k = 4*tig + 0..3 within a 16-k step),
// feeding TWO m16n8k8 MMAs:
//   MMA0: frag kloc = 4*tig, 4*tig+1   (a = v.x, v.y)
//   MMA1: frag kloc = 4*tig+2, 4*tig+3 (a = v.z, v.w)
// B staged in smem at row stride 22 words -> B LDS are bank-conflict-free
// (bank = 24*tig + 8*t + gid mod 32 covers all banks). Unwritten row words
// 20..21 / pad only ever feed discarded D cols 20..23.
// ---------------------------------------------------------------------------
__global__ void __launch_bounds__(256)
spmm_part_kernel(const float* __restrict__ adj,
                 const float* __restrict__ T,
                 float* __restrict__ part)
{
    __shared__ uint32_t Ts[TS_WORDS];

    const int tid  = threadIdx.x;
    const int warp = tid >> 5;
    const int lane = tid & 31;
    const int gid  = lane >> 2;   // 0..7  (row-in-group)
    const int tig  = lane & 3;    // 0..3  (k selector)
    const int tig4 = 4 * tig;
    const int tig2 = 2 * tig;

    // zero the tail pad (row-399 col-overhang reads land here)
    if (tid < 32) Ts[SLAB * BSTRIDE + tid] = 0;

    const int strip  = blockIdx.x * STRIPS_PER_BLK + warp;
    const bool active = (strip < NSTRIPS);
    const int m0   = strip * 16;
    const int slab = blockIdx.y;
    const int rbase = active ? (m0 + gid) : 0;

    const float* a_row0 = adj + (size_t)rbase * KDIM + (size_t)slab * SLAB;
    const float* a_row1 = a_row0 + (size_t)8 * KDIM;

    // stage B slab (400 rows x 20 floats, contiguous in T) as tf32 @ stride 22
    {
        const float4* src = (const float4*)(T + (size_t)slab * SLAB * F);
#pragma unroll
        for (int it = 0; it < (SLAB * F) / 4 / 256 + 1; ++it) {
            int i = it * 256 + tid;
            if (i < (SLAB * F) / 4) {
                const int row = i / 5;          // 5 float4 per 20-float row
                const int cf  = i % 5;
                float4 v = src[i];
                uint2 lo = make_uint2(f2tf(v.x), f2tf(v.y));
                uint2 hi = make_uint2(f2tf(v.z), f2tf(v.w));
                uint32_t* dst = &Ts[row * BSTRIDE + 4 * cf];
                *(uint2*)(dst)     = lo;        // 8-B aligned (88*row+16*cf)
                *(uint2*)(dst + 2) = hi;
            }
        }
    }

    float acc[3][4];
#pragma unroll
    for (int t = 0; t < 3; t++)
#pragma unroll
        for (int j = 0; j < 4; j++) acc[t][j] = 0.0f;

    // A-load register ring (PF wide-steps deep, float4 per row-half)
    float4 ra[PF], rb[PF];
#pragma unroll
    for (int p = 0; p < PF; p++) {
        const int off = p * 16 + tig4;
        ra[p] = *(const float4*)(a_row0 + off);
        rb[p] = *(const float4*)(a_row1 + off);
    }

    __syncthreads();   // staging visible to all warps

    if (active) {
#pragma unroll
        for (int ss = 0; ss < WSTEPS; ++ss) {
            const int slot = ss & (PF - 1);     // PF=4, compile-time

            const float4 va = ra[slot];
            const float4 vb = rb[slot];

            // prefetch wide-step ss+PF
            {
                const int nko = (ss + PF) * 16 + tig4;
                const int po  = (nko < SLAB) ? nko : tig4;   // tail dummy
                ra[slot] = *(const float4*)(a_row0 + po);
                rb[slot] = *(const float4*)(a_row1 + po);
            }

            // MMA0 fragments: kloc = 4tig, 4tig+1
            const uint32_t p0a0 = f2tf(va.x), p0a2 = f2tf(va.y);
            const uint32_t p0a1 = f2tf(vb.x), p0a3 = f2tf(vb.y);
            // MMA1 fragments: kloc = 4tig+2, 4tig+3
            const uint32_t p1a0 = f2tf(va.z), p1a2 = f2tf(va.w);
            const uint32_t p1a1 = f2tf(vb.z), p1a3 = f2tf(vb.w);

            const int rbase_w = (ss * 16 + tig4) * BSTRIDE;
#pragma unroll
            for (int t = 0; t < 3; t++) {
                const int cn = 8 * t + gid;
                uint32_t b00 = Ts[rbase_w + cn];                 // kloc 4tig
                uint32_t b01 = Ts[rbase_w + BSTRIDE + cn];       // kloc 4tig+1
                asm volatile(
                    "mma.sync.aligned.m16n8k8.row.col.f32.tf32.tf32.f32 "
                    "{%0,%1,%2,%3},{%4,%5,%6,%7},{%8,%9},{%0,%1,%2,%3};"
                    : "+f"(acc[t][0]), "+f"(acc[t][1]),
                      "+f"(acc[t][2]), "+f"(acc[t][3])
                    : "r"(p0a0), "r"(p0a1), "r"(p0a2), "r"(p0a3),
                      "r"(b00), "r"(b01));
                uint32_t b10 = Ts[rbase_w + 2 * BSTRIDE + cn];   // kloc 4tig+2
                uint32_t b11 = Ts[rbase_w + 3 * BSTRIDE + cn];   // kloc 4tig+3
                asm volatile(
                    "mma.sync.aligned.m16n8k8.row.col.f32.tf32.tf32.f32 "
                    "{%0,%1,%2,%3},{%4,%5,%6,%7},{%8,%9},{%0,%1,%2,%3};"
                    : "+f"(acc[t][0]), "+f"(acc[t][1]),
                      "+f"(acc[t][2]), "+f"(acc[t][3])
                    : "r"(p1a0), "r"(p1a1), "r"(p1a2), "r"(p1a3),
                      "r"(b10), "r"(b11));
            }
        }

        float* po = part + (size_t)slab * NROWS * F;
#pragma unroll
        for (int t = 0; t < 3; t++) {
            const int c = 8 * t + tig2;   // col pairs never straddle 20
            if (c < F) {
                const int r0 = m0 + gid;
                const int r1 = r0 + 8;
                *(float2*)(po + (size_t)r0 * F + c) =
                    make_float2(acc[t][0], acc[t][1]);
                *(float2*)(po + (size_t)r1 * F + c) =
                    make_float2(acc[t][2], acc[t][3]);
            }
        }
    }
}

// ---------------------------------------------------------------------------
// Reduce partials: out[i] = relu( sum_s part[s][i] + bias[i%20] )
// ---------------------------------------------------------------------------
__global__ void __launch_bounds__(256)
reduce_kernel(const float* __restrict__ part, const float* __restrict__ bias,
              float* __restrict__ out)
{
    const int i = blockIdx.x * 256 + threadIdx.x;
    if (i < NROWS * F) {
        float s = 0.f;
#pragma unroll
        for (int sl = 0; sl < SPLIT; sl++)
            s += part[(size_t)sl * NROWS * F + i];
        out[i] = fmaxf(s + bias[i % F], 0.f);
    }
}

// ---------------------------------------------------------------------------
// Small GEMM: T[N,20] = Hin[N,KK] @ W[KK,20].  Warp per row, lane = out col.
// ---------------------------------------------------------------------------
template <int KK>
__global__ void __launch_bounds__(256)
xw_kernel(const float* __restrict__ Hin, const float* __restrict__ W,
          float* __restrict__ T)
{
    __shared__ float Ws[KK * F];
    const int tid = threadIdx.x;
    for (int i = tid; i < KK * F; i += 256) Ws[i] = W[i];
    __syncthreads();

    const int warp = tid >> 5;
    const int lane = tid & 31;
    const int row  = blockIdx.x * 8 + warp;   // grid*8 == NROWS exactly

    const float* h = Hin + (size_t)row * KK;
    if (lane < F) {
        float a0 = 0.f, a1 = 0.f, a2 = 0.f, a3 = 0.f;
#pragma unroll 4
        for (int k = 0; k < KK; k += 4) {
            a0 += h[k + 0] * Ws[(k + 0) * F + lane];
            a1 += h[k + 1] * Ws[(k + 1) * F + lane];
            a2 += h[k + 2] * Ws[(k + 2) * F + lane];
            a3 += h[k + 3] * Ws[(k + 3) * F + lane];
        }
        T[(size_t)row * F + lane] = (a0 + a1) + (a2 + a3);
    }
}

// ---------------------------------------------------------------------------
// Final (fused partial-reduce): out = relu( relu((sum_s P_s) @ W3 + b3) + x )
// ---------------------------------------------------------------------------
__global__ void __launch_bounds__(256)
final_kernel(const float* __restrict__ P, const float* __restrict__ W3,
             const float* __restrict__ b3, const float* __restrict__ x,
             float* __restrict__ out)
{
    __shared__ float Ws[F * D];    // 20 x 128
    __shared__ float ps[2 * F];    // reduced P rows for this block
    const int tid = threadIdx.x;
    for (int i = tid; i < F * D; i += 256) Ws[i] = W3[i];

    const int row0 = blockIdx.x * 2;
    if (tid < 2 * F) {
        const int r = tid / F, c = tid % F;
        float s = 0.f;
#pragma unroll
        for (int sl = 0; sl < SPLIT; sl++)
            s += P[(size_t)sl * NROWS * F + (size_t)(row0 + r) * F + c];
        ps[tid] = s;
    }
    __syncthreads();

    const int r   = tid >> 7;
    const int col = tid & 127;

    float acc = b3[col];
#pragma unroll
    for (int k = 0; k < F; k++) acc += ps[r * F + k] * Ws[k * D + col];

    const float h = fmaxf(acc, 0.f);
    const size_t o = (size_t)(row0 + r) * D + col;
    out[o] = fmaxf(h + x[o], 0.f);
}

// ---------------------------------------------------------------------------
extern "C" void kernel_launch(void* const* d_in, const int* in_sizes, int n_in,
                              void* d_out, int out_size)
{
    const float* x   = (const float*)d_in[0];
    const float* adj = (const float*)d_in[1];
    const float* W1  = (const float*)d_in[2];
    const float* b1  = (const float*)d_in[3];
    const float* W2  = (const float*)d_in[4];
    const float* b2  = (const float*)d_in[5];
    const float* W3  = (const float*)d_in[6];
    const float* b3  = (const float*)d_in[7];
    float* out = (float*)d_out;

    float *T, *H, *P;
    cudaGetSymbolAddress((void**)&T, g_bufT);
    cudaGetSymbolAddress((void**)&H, g_bufH);
    cudaGetSymbolAddress((void**)&P, g_part);

    const dim3 SPMM_GRID(NSTRIP_GROUPS, SPLIT);      // 79 x 25 blocks, 256 thr
    const int  RED_GRID = (NROWS * F + 255) / 256;   // 782

    // T1 = x @ W1
    xw_kernel<D><<<NROWS / 8, 256>>>(x, W1, T);
    // H1 = relu(adj @ T1 + b1)
    spmm_part_kernel<<<SPMM_GRID, 256>>>(adj, T, P);
    reduce_kernel<<<RED_GRID, 256>>>(P, b1, H);
    // T2 = H1 @ W2
    xw_kernel<F><<<NROWS / 8, 256>>>(H, W2, T);
    // H2 = relu(adj @ T2 + b2)
    spmm_part_kernel<<<SPMM_GRID, 256>>>(adj, T, P);
    reduce_kernel<<<RED_GRID, 256>>>(P, b2, H);
    // P = partials of adj @ H2
    spmm_part_kernel<<<SPMM_GRID, 256>>>(adj, H, P);
    // out = relu(relu(sum(P) @ W3 + b3) + x)
    final_kernel<<<NROWS / 2, 256>>>(P, W3, b3, x, out);
}

// round 8
// speedup vs baseline: 1.7074x; 1.2006x over previous
#include <cuda_runtime.h>
#include <cuda_fp16.h>
#include <cstdint>

// Problem constants
#define NROWS 10000
#define KDIM  10000
#define KH    10240     // fp16 adj padded row stride (zeros beyond 10000)
#define F     20        // hidden width
#define D     128       // in/out width
#define NSTRIPS ((NROWS + 15) / 16)   // 625 (exact)

// K-split over the padded fp16 matrix: 20 slabs of 512 cols (32 | 512)
#define SPLIT  20
#define SLAB   512
#define SSTEPS (SLAB / 32)      // 16 supersteps (4 MMAs each)
#define STRIPS_PER_BLK 8
#define NSTRIP_GROUPS ((NSTRIPS + STRIPS_PER_BLK - 1) / STRIPS_PER_BLK)  // 79
#define PF 4                    // A-load ring depth (supersteps)

#define BSTRIDE 21              // B smem row stride (conflict-free LDS)
#define TS_WORDS (SLAB * BSTRIDE + 32)

// Scratch (no allocations allowed)
__device__ float  g_bufT[NROWS * F];
__device__ float  g_bufH[NROWS * F];
__device__ float  g_part[SPLIT * NROWS * F];        // 16 MB partials
__device__ __half g_adjh[(size_t)NROWS * KH];       // 204.8 MB fp16 adj

__device__ __forceinline__ uint32_t f2tf(float f) {
    uint32_t u;
    asm("cvt.rna.tf32.f32 %0, %1;" : "=r"(u) : "f"(f));
    return u;
}

// ---------------------------------------------------------------------------
// Convert adj (fp32, stride 10000) -> g_adjh (fp16, stride 10240, zero pad).
// Pure streaming: 2x16 B loads + 16 B store per thread op, fully coalesced.
// ---------------------------------------------------------------------------
__global__ void __launch_bounds__(256)
convert_kernel(const float* __restrict__ adj)
{
    const size_t total = (size_t)NROWS * (KH / 8);   // thread-ops of 8 cols
    for (size_t i = (size_t)blockIdx.x * 256 + threadIdx.x; i < total;
         i += (size_t)gridDim.x * 256) {
        const int r  = (int)(i / (KH / 8));
        const int c8 = (int)(i % (KH / 8));
        uint4* dst = (uint4*)(g_adjh + (size_t)r * KH + c8 * 8);
        if (c8 < KDIM / 8) {
            const float4* src = (const float4*)(adj + (size_t)r * KDIM + c8 * 8);
            float4 v0 = src[0], v1 = src[1];
            __half2 h0 = __floats2half2_rn(v0.x, v0.y);
            __half2 h1 = __floats2half2_rn(v0.z, v0.w);
            __half2 h2 = __floats2half2_rn(v1.x, v1.y);
            __half2 h3 = __floats2half2_rn(v1.z, v1.w);
            uint4 w;
            w.x = *(uint32_t*)&h0; w.y = *(uint32_t*)&h1;
            w.z = *(uint32_t*)&h2; w.w = *(uint32_t*)&h3;
            *dst = w;
        } else {
            *dst = make_uint4(0, 0, 0, 0);
        }
    }
}

// ---------------------------------------------------------------------------
// Big GEMM partial (fp16 A): part[slab][N,20] = adjh[:, slab] @ T[slab, 20]
// Per-warp 16-row strip over one 512-col slab; 8 warps/block share staging.
// Each lane loads uint4 = 8 halves = k in [8*tig, 8*tig+8) per 32-k superstep,
// feeding FOUR m16n8k8 MMAs. Per MMA j (j=0..3), k-slot map (same for A & B):
//   slot tig   <-> global k = 8*tig + 2j     (a0/a1 from rows gid / gid+8)
//   slot tig+4 <-> global k = 8*tig + 2j + 1 (a2/a3)
// Because A and B use the same permutation, the dot product is exact.
// B staged at row stride 21 words: LDS addr = (8tig+2j)*21 + 8t + gid ->
// bank = (168*tig + ...) mod 32 = (8*tig + gid + const) mod 32, distinct for
// all 32 lanes -> conflict-free. Row word 20 garbage + pad only ever feed
// discarded D cols 20..23.
// ---------------------------------------------------------------------------
__global__ void __launch_bounds__(256)
spmm_part_kernel(const float* __restrict__ T,
                 float* __restrict__ part)
{
    __shared__ uint32_t Ts[TS_WORDS];

    const int tid  = threadIdx.x;
    const int warp = tid >> 5;
    const int lane = tid & 31;
    const int gid  = lane >> 2;   // 0..7  (row-in-group / B col)
    const int tig  = lane & 3;    // 0..3  (k selector)
    const int tig2 = 2 * tig;

    if (tid < 32) Ts[SLAB * BSTRIDE + tid] = 0;   // pad for col-overhang

    const int strip  = blockIdx.x * STRIPS_PER_BLK + warp;
    const bool active = (strip < NSTRIPS);
    const int m0   = strip * 16;
    const int slab = blockIdx.y;
    const int rbase = active ? (m0 + gid) : 0;

    const __half* a_row0 = g_adjh + (size_t)rbase * KH + (size_t)slab * SLAB;
    const __half* a_row1 = a_row0 + (size_t)8 * KH;

    // stage B slab (512 rows x 20 floats, contiguous in T) as tf32 @ stride 21
    {
        const float4* src = (const float4*)(T + (size_t)slab * SLAB * F);
#pragma unroll
        for (int it = 0; it < (SLAB * F) / 4 / 256; ++it) {
            const int i   = it * 256 + tid;
            const int row = i / 5;          // 5 float4 per 20-float row
            const int cf  = i % 5;
            float4 v = src[i];
            uint32_t* dst = &Ts[row * BSTRIDE + 4 * cf];
            dst[0] = f2tf(v.x); dst[1] = f2tf(v.y);
            dst[2] = f2tf(v.z); dst[3] = f2tf(v.w);
        }
    }

    float acc[3][4];
#pragma unroll
    for (int t = 0; t < 3; t++)
#pragma unroll
        for (int j = 0; j < 4; j++) acc[t][j] = 0.0f;

    // A-load register ring (PF supersteps deep; uint4 = 8 halves per row-half)
    uint4 ra[PF], rb[PF];
#pragma unroll
    for (int p = 0; p < PF; p++) {
        const int off = p * 32 + 8 * tig;
        ra[p] = *(const uint4*)(a_row0 + off);
        rb[p] = *(const uint4*)(a_row1 + off);
    }

    __syncthreads();   // staging visible to all warps

    if (active) {
#pragma unroll 4
        for (int ss = 0; ss < SSTEPS; ++ss) {
            const int slot = ss & (PF - 1);

            const uint4 va = ra[slot];
            const uint4 vb = rb[slot];

            // prefetch superstep ss+PF (tail reads re-fetch a dummy in-bounds)
            {
                const int nko = (ss + PF) * 32 + 8 * tig;
                const int po  = (nko < SLAB) ? nko : 8 * tig;
                ra[slot] = *(const uint4*)(a_row0 + po);
                rb[slot] = *(const uint4*)(a_row1 + po);
            }

            const uint32_t va_h2[4] = {va.x, va.y, va.z, va.w};
            const uint32_t vb_h2[4] = {vb.x, vb.y, vb.z, vb.w};
            const int krow0 = (ss * 32 + 8 * tig) * BSTRIDE;

#pragma unroll
            for (int j = 0; j < 4; j++) {
                // fp16 values are exact in tf32 -> convert & reinterpret
                const float2 fa = __half22float2(*(const __half2*)&va_h2[j]);
                const float2 fb = __half22float2(*(const __half2*)&vb_h2[j]);
                const uint32_t a0 = __float_as_uint(fa.x);  // k = 8tig+2j
                const uint32_t a2 = __float_as_uint(fa.y);  // k = 8tig+2j+1
                const uint32_t a1 = __float_as_uint(fb.x);
                const uint32_t a3 = __float_as_uint(fb.y);

                const int r0 = krow0 + 2 * j * BSTRIDE;
#pragma unroll
                for (int t = 0; t < 3; t++) {
                    const int cn = 8 * t + gid;
                    uint32_t b0 = Ts[r0 + cn];            // k = 8tig+2j
                    uint32_t b1 = Ts[r0 + BSTRIDE + cn];  // k = 8tig+2j+1
                    asm volatile(
                        "mma.sync.aligned.m16n8k8.row.col.f32.tf32.tf32.f32 "
                        "{%0,%1,%2,%3},{%4,%5,%6,%7},{%8,%9},{%0,%1,%2,%3};"
                        : "+f"(acc[t][0]), "+f"(acc[t][1]),
                          "+f"(acc[t][2]), "+f"(acc[t][3])
                        : "r"(a0), "r"(a1), "r"(a2), "r"(a3),
                          "r"(b0), "r"(b1));
                }
            }
        }

        float* po = part + (size_t)slab * NROWS * F;
#pragma unroll
        for (int t = 0; t < 3; t++) {
            const int c = 8 * t + tig2;   // col pairs never straddle 20
            if (c < F) {
                const int r0 = m0 + gid;
                const int r1 = r0 + 8;
                *(float2*)(po + (size_t)r0 * F + c) =
                    make_float2(acc[t][0], acc[t][1]);
                *(float2*)(po + (size_t)r1 * F + c) =
                    make_float2(acc[t][2], acc[t][3]);
            }
        }
    }
}

// ---------------------------------------------------------------------------
// Reduce partials: out[i] = relu( sum_s part[s][i] + bias[i%20] )
// ---------------------------------------------------------------------------
__global__ void __launch_bounds__(256)
reduce_kernel(const float* __restrict__ part, const float* __restrict__ bias,
              float* __restrict__ out)
{
    const int i = blockIdx.x * 256 + threadIdx.x;
    if (i < NROWS * F) {
        float s = 0.f;
#pragma unroll
        for (int sl = 0; sl < SPLIT; sl++)
            s += part[(size_t)sl * NROWS * F + i];
        out[i] = fmaxf(s + bias[i % F], 0.f);
    }
}

// ---------------------------------------------------------------------------
// Small GEMM: T[N,20] = Hin[N,KK] @ W[KK,20].  Warp per row, lane = out col.
// ---------------------------------------------------------------------------
template <int KK>
__global__ void __launch_bounds__(256)
xw_kernel(const float* __restrict__ Hin, const float* __restrict__ W,
          float* __restrict__ T)
{
    __shared__ float Ws[KK * F];
    const int tid = threadIdx.x;
    for (int i = tid; i < KK * F; i += 256) Ws[i] = W[i];
    __syncthreads();

    const int warp = tid >> 5;
    const int lane = tid & 31;
    const int row  = blockIdx.x * 8 + warp;   // grid*8 == NROWS exactly

    const float* h = Hin + (size_t)row * KK;
    if (lane < F) {
        float a0 = 0.f, a1 = 0.f, a2 = 0.f, a3 = 0.f;
#pragma unroll 4
        for (int k = 0; k < KK; k += 4) {
            a0 += h[k + 0] * Ws[(k + 0) * F + lane];
            a1 += h[k + 1] * Ws[(k + 1) * F + lane];
            a2 += h[k + 2] * Ws[(k + 2) * F + lane];
            a3 += h[k + 3] * Ws[(k + 3) * F + lane];
        }
        T[(size_t)row * F + lane] = (a0 + a1) + (a2 + a3);
    }
}

// ---------------------------------------------------------------------------
// Final (fused partial-reduce): out = relu( relu((sum_s P_s) @ W3 + b3) + x )
// ---------------------------------------------------------------------------
__global__ void __launch_bounds__(256)
final_kernel(const float* __restrict__ P, const float* __restrict__ W3,
             const float* __restrict__ b3, const float* __restrict__ x,
             float* __restrict__ out)
{
    __shared__ float Ws[F * D];    // 20 x 128
    __shared__ float ps[2 * F];    // reduced P rows for this block
    const int tid = threadIdx.x;
    for (int i = tid; i < F * D; i += 256) Ws[i] = W3[i];

    const int row0 = blockIdx.x * 2;
    if (tid < 2 * F) {
        const int r = tid / F, c = tid % F;
        float s = 0.f;
#pragma unroll
        for (int sl = 0; sl < SPLIT; sl++)
            s += P[(size_t)sl * NROWS * F + (size_t)(row0 + r) * F + c];
        ps[tid] = s;
    }
    __syncthreads();

    const int r   = tid >> 7;
    const int col = tid & 127;

    float acc = b3[col];
#pragma unroll
    for (int k = 0; k < F; k++) acc += ps[r * F + k] * Ws[k * D + col];

    const float h = fmaxf(acc, 0.f);
    const size_t o = (size_t)(row0 + r) * D + col;
    out[o] = fmaxf(h + x[o], 0.f);
}

// ---------------------------------------------------------------------------
extern "C" void kernel_launch(void* const* d_in, const int* in_sizes, int n_in,
                              void* d_out, int out_size)
{
    const float* x   = (const float*)d_in[0];
    const float* adj = (const float*)d_in[1];
    const float* W1  = (const float*)d_in[2];
    const float* b1  = (const float*)d_in[3];
    const float* W2  = (const float*)d_in[4];
    const float* b2  = (const float*)d_in[5];
    const float* W3  = (const float*)d_in[6];
    const float* b3  = (const float*)d_in[7];
    float* out = (float*)d_out;

    float *T, *H, *P;
    cudaGetSymbolAddress((void**)&T, g_bufT);
    cudaGetSymbolAddress((void**)&H, g_bufH);
    cudaGetSymbolAddress((void**)&P, g_part);

    const dim3 SPMM_GRID(NSTRIP_GROUPS, SPLIT);      // 79 x 20 blocks, 256 thr
    const int  RED_GRID = (NROWS * F + 255) / 256;   // 782

    // fp16 copy of adj (padded to 10240 cols with zeros)
    convert_kernel<<<2960, 256>>>(adj);
    // T1 = x @ W1
    xw_kernel<D><<<NROWS / 8, 256>>>(x, W1, T);
    // H1 = relu(adj @ T1 + b1)
    spmm_part_kernel<<<SPMM_GRID, 256>>>(T, P);
    reduce_kernel<<<RED_GRID, 256>>>(P, b1, H);
    // T2 = H1 @ W2
    xw_kernel<F><<<NROWS / 8, 256>>>(H, W2, T);
    // H2 = relu(adj @ T2 + b2)
    spmm_part_kernel<<<SPMM_GRID, 256>>>(T, P);
    reduce_kernel<<<RED_GRID, 256>>>(P, b2, H);
    // P = partials of adj @ H2
    spmm_part_kernel<<<SPMM_GRID, 256>>>(H, P);
    // out = relu(relu(sum(P) @ W3 + b3) + x)
    final_kernel<<<NROWS / 2, 256>>>(P, W3, b3, x, out);
}

// round 10
// speedup vs baseline: 1.7885x; 1.0475x over previous
#include <cuda_runtime.h>
#include <cuda_fp16.h>
#include <cstdint>

// Problem constants
#define NROWS 10000
#define KDIM  10000
#define KH    10240     // fp16 adj padded cols (zeros beyond 10000)
#define F     20        // hidden width
#define D     128       // in/out width
#define NSTRIPS ((NROWS + 15) / 16)   // 625 (exact)

// K-split over the padded fp16 matrix: 20 slabs of 512 cols (32 | 512)
#define SPLIT  20
#define SLAB   512
#define SSTEPS (SLAB / 32)      // 16 supersteps (4 MMAs each)
#define TILE_HALVES (16 * SLAB) // 8192 halves = 16 KB per (strip,slab) tile
#define STRIPS_PER_BLK 8
#define NSTRIP_GROUPS ((NSTRIPS + STRIPS_PER_BLK - 1) / STRIPS_PER_BLK)  // 79
#define PF 4                    // A-load ring depth (supersteps)

// Intra-tile offsets IN HALVES (16 B per lane-slot):
//   slot(tig)   stride =   8 halves
//   gid         stride =  32 halves
//   half(row8)  stride = 256 halves
//   superstep   stride = 512 halves   (16 ss * 512 = 8192 = TILE_HALVES)
#define OFF_TIG   8
#define OFF_GID   32
#define OFF_HALF  256
#define OFF_SS    512

#define BSTRIDE 21              // B smem row stride (conflict-free LDS)
#define TS_WORDS (SLAB * BSTRIDE + 32)

// Scratch (no allocations allowed)
__device__ float  g_bufT[NROWS * F];
__device__ float  g_bufH[NROWS * F];
__device__ float  g_part[SPLIT * NROWS * F];        // 16 MB partials
// Tiled fp16 adj: [strip 625][slab 20][ss 16][half 2][gid 8][tig 4][8 halves]
__device__ __half g_adjh[(size_t)NROWS * KH];       // 204.8 MB

__device__ __forceinline__ uint32_t f2tf(float f) {
    uint32_t u;
    asm("cvt.rna.tf32.f32 %0, %1;" : "=r"(u) : "f"(f));
    return u;
}

// ---------------------------------------------------------------------------
// Convert adj (fp32, row-major) -> g_adjh (fp16, warp-tiled layout).
// Tile (strip, slab) holds rows [16*strip,16*strip+16) x cols [512*slab, ...).
// Internal order [ss][half][gid][tig][8 halves]: spmm's warp fetch for a
// superstep is 512 B contiguous with per-lane offset = lane*16 B.
// ---------------------------------------------------------------------------
__global__ void __launch_bounds__(256)
convert_kernel(const float* __restrict__ adj)
{
    const size_t total = (size_t)NROWS * (KH / 8);   // thread-ops of 8 cols
    for (size_t i = (size_t)blockIdx.x * 256 + threadIdx.x; i < total;
         i += (size_t)gridDim.x * 256) {
        const int r  = (int)(i / (KH / 8));
        const int c8 = (int)(i % (KH / 8));
        const int c  = c8 * 8;               // padded col of first element

        // destination inside the tiled layout
        const int strip = r >> 4;
        const int slab  = c / SLAB;
        const int cs    = c % SLAB;          // col within slab (multiple of 8)
        const int ss    = cs >> 5;           // superstep
        const int tig   = (cs & 31) >> 3;
        const int half  = (r & 15) >> 3;
        const int gid   = r & 7;
        __half* dst = g_adjh
            + ((size_t)strip * SPLIT + slab) * TILE_HALVES
            + ss * OFF_SS + half * OFF_HALF + gid * OFF_GID + tig * OFF_TIG;

        if (c < KDIM) {
            const float4* src = (const float4*)(adj + (size_t)r * KDIM + c);
            float4 v0 = src[0], v1 = src[1];
            __half2 h0 = __floats2half2_rn(v0.x, v0.y);
            __half2 h1 = __floats2half2_rn(v0.z, v0.w);
            __half2 h2 = __floats2half2_rn(v1.x, v1.y);
            __half2 h3 = __floats2half2_rn(v1.z, v1.w);
            uint4 w;
            w.x = *(uint32_t*)&h0; w.y = *(uint32_t*)&h1;
            w.z = *(uint32_t*)&h2; w.w = *(uint32_t*)&h3;
            *(uint4*)dst = w;
        } else {
            *(uint4*)dst = make_uint4(0, 0, 0, 0);
        }
    }
}

// ---------------------------------------------------------------------------
// Big GEMM partial (tiled fp16 A): part[slab][N,20] = adj[:,slab] @ T[slab,20]
// Per-warp 16-row strip over one 512-col slab; 8 warps/block share B staging.
// A: each superstep the warp does TWO 512-B contiguous lane-linear fetches
// (half 0 = rows gid, half 1 = rows gid+8) from its private 16 KB tile ->
// pure sequential streaming. Per MMA j (j=0..3), k-slot map (same for A & B):
//   slot tig   <-> k = 8*tig + 2j,  slot tig+4 <-> k = 8*tig + 2j + 1
// B staged at row stride 21 words -> conflict-free LDS; row word 20 garbage
// and pad only feed discarded D cols 20..23.
// ---------------------------------------------------------------------------
__global__ void __launch_bounds__(256)
spmm_part_kernel(const float* __restrict__ T,
                 float* __restrict__ part)
{
    __shared__ uint32_t Ts[TS_WORDS];

    const int tid  = threadIdx.x;
    const int warp = tid >> 5;
    const int lane = tid & 31;
    const int gid  = lane >> 2;   // 0..7  (row-in-group / B col)
    const int tig  = lane & 3;    // 0..3  (k selector)
    const int tig2 = 2 * tig;

    if (tid < 32) Ts[SLAB * BSTRIDE + tid] = 0;   // pad for col-overhang

    const int strip  = blockIdx.x * STRIPS_PER_BLK + warp;
    const bool active = (strip < NSTRIPS);
    const int strip_c = active ? strip : (NSTRIPS - 1);   // clamp pointers
    const int m0   = strip * 16;
    const int slab = blockIdx.y;

    const __half* tile = g_adjh
        + ((size_t)strip_c * SPLIT + slab) * TILE_HALVES
        + lane * OFF_TIG;                  // lane-linear base (16 B per lane)

    // stage B slab (512 rows x 20 floats, contiguous in T) as tf32 @ stride 21
    {
        const float4* src = (const float4*)(T + (size_t)slab * SLAB * F);
#pragma unroll
        for (int it = 0; it < (SLAB * F) / 4 / 256; ++it) {
            const int i   = it * 256 + tid;
            const int row = i / 5;          // 5 float4 per 20-float row
            const int cf  = i % 5;
            float4 v = src[i];
            uint32_t* dst = &Ts[row * BSTRIDE + 4 * cf];
            dst[0] = f2tf(v.x); dst[1] = f2tf(v.y);
            dst[2] = f2tf(v.z); dst[3] = f2tf(v.w);
        }
    }

    float acc[3][4];
#pragma unroll
    for (int t = 0; t < 3; t++)
#pragma unroll
        for (int j = 0; j < 4; j++) acc[t][j] = 0.0f;

    // A-load register ring (PF supersteps deep; uint4 = 8 halves per half-row)
    uint4 ra[PF], rb[PF];
#pragma unroll
    for (int p = 0; p < PF; p++) {
        ra[p] = *(const uint4*)(tile + p * OFF_SS);
        rb[p] = *(const uint4*)(tile + p * OFF_SS + OFF_HALF);
    }

    __syncthreads();   // staging visible to all warps

    if (active) {
#pragma unroll 4
        for (int ss = 0; ss < SSTEPS; ++ss) {
            const int slot = ss & (PF - 1);

            const uint4 va = ra[slot];
            const uint4 vb = rb[slot];

            // prefetch superstep ss+PF (tail re-reads a dummy in-bounds spot)
            {
                const int nss = ss + PF;
                const int po  = (nss < SSTEPS) ? nss * OFF_SS : 0;
                ra[slot] = *(const uint4*)(tile + po);
                rb[slot] = *(const uint4*)(tile + po + OFF_HALF);
            }

            const uint32_t va_h2[4] = {va.x, va.y, va.z, va.w};
            const uint32_t vb_h2[4] = {vb.x, vb.y, vb.z, vb.w};
            const int krow0 = (ss * 32 + 8 * tig) * BSTRIDE;

#pragma unroll
            for (int j = 0; j < 4; j++) {
                // fp16 values are exact in tf32 -> convert & reinterpret
                const float2 fa = __half22float2(*(const __half2*)&va_h2[j]);
                const float2 fb = __half22float2(*(const __half2*)&vb_h2[j]);
                const uint32_t a0 = __float_as_uint(fa.x);  // k = 8tig+2j
                const uint32_t a2 = __float_as_uint(fa.y);  // k = 8tig+2j+1
                const uint32_t a1 = __float_as_uint(fb.x);
                const uint32_t a3 = __float_as_uint(fb.y);

                const int r0 = krow0 + 2 * j * BSTRIDE;
#pragma unroll
                for (int t = 0; t < 3; t++) {
                    const int cn = 8 * t + gid;
                    uint32_t b0 = Ts[r0 + cn];            // k = 8tig+2j
                    uint32_t b1 = Ts[r0 + BSTRIDE + cn];  // k = 8tig+2j+1
                    asm volatile(
                        "mma.sync.aligned.m16n8k8.row.col.f32.tf32.tf32.f32 "
                        "{%0,%1,%2,%3},{%4,%5,%6,%7},{%8,%9},{%0,%1,%2,%3};"
                        : "+f"(acc[t][0]), "+f"(acc[t][1]),
                          "+f"(acc[t][2]), "+f"(acc[t][3])
                        : "r"(a0), "r"(a1), "r"(a2), "r"(a3),
                          "r"(b0), "r"(b1));
                }
            }
        }

        float* po = part + (size_t)slab * NROWS * F;
#pragma unroll
        for (int t = 0; t < 3; t++) {
            const int c = 8 * t + tig2;   // col pairs never straddle 20
            if (c < F) {
                const int r0 = m0 + gid;
                const int r1 = r0 + 8;
                *(float2*)(po + (size_t)r0 * F + c) =
                    make_float2(acc[t][0], acc[t][1]);
                *(float2*)(po + (size_t)r1 * F + c) =
                    make_float2(acc[t][2], acc[t][3]);
            }
        }
    }
}

// ---------------------------------------------------------------------------
// Reduce partials: out[i] = relu( sum_s part[s][i] + bias[i%20] )
// ---------------------------------------------------------------------------
__global__ void __launch_bounds__(256)
reduce_kernel(const float* __restrict__ part, const float* __restrict__ bias,
              float* __restrict__ out)
{
    const int i = blockIdx.x * 256 + threadIdx.x;
    if (i < NROWS * F) {
        float s = 0.f;
#pragma unroll
        for (int sl = 0; sl < SPLIT; sl++)
            s += part[(size_t)sl * NROWS * F + i];
        out[i] = fmaxf(s + bias[i % F], 0.f);
    }
}

// ---------------------------------------------------------------------------
// Small GEMM: T[N,20] = Hin[N,KK] @ W[KK,20].  Warp per row, lane = out col.
// ---------------------------------------------------------------------------
template <int KK>
__global__ void __launch_bounds__(256)
xw_kernel(const float* __restrict__ Hin, const float* __restrict__ W,
          float* __restrict__ T)
{
    __shared__ float Ws[KK * F];
    const int tid = threadIdx.x;
    for (int i = tid; i < KK * F; i += 256) Ws[i] = W[i];
    __syncthreads();

    const int warp = tid >> 5;
    const int lane = tid & 31;
    const int row  = blockIdx.x * 8 + warp;   // grid*8 == NROWS exactly

    const float* h = Hin + (size_t)row * KK;
    if (lane < F) {
        float a0 = 0.f, a1 = 0.f, a2 = 0.f, a3 = 0.f;
#pragma unroll 4
        for (int k = 0; k < KK; k += 4) {
            a0 += h[k + 0] * Ws[(k + 0) * F + lane];
            a1 += h[k + 1] * Ws[(k + 1) * F + lane];
            a2 += h[k + 2] * Ws[(k + 2) * F + lane];
            a3 += h[k + 3] * Ws[(k + 3) * F + lane];
        }
        T[(size_t)row * F + lane] = (a0 + a1) + (a2 + a3);
    }
}

// ---------------------------------------------------------------------------
// Final (fused partial-reduce): out = relu( relu((sum_s P_s) @ W3 + b3) + x )
// ---------------------------------------------------------------------------
__global__ void __launch_bounds__(256)
final_kernel(const float* __restrict__ P, const float* __restrict__ W3,
             const float* __restrict__ b3, const float* __restrict__ x,
             float* __restrict__ out)
{
    __shared__ float Ws[F * D];    // 20 x 128
    __shared__ float ps[2 * F];    // reduced P rows for this block
    const int tid = threadIdx.x;
    for (int i = tid; i < F * D; i += 256) Ws[i] = W3[i];

    const int row0 = blockIdx.x * 2;
    if (tid < 2 * F) {
        const int r = tid / F, c = tid % F;
        float s = 0.f;
#pragma unroll
        for (int sl = 0; sl < SPLIT; sl++)
            s += P[(size_t)sl * NROWS * F + (size_t)(row0 + r) * F + c];
        ps[tid] = s;
    }
    __syncthreads();

    const int r   = tid >> 7;
    const int col = tid & 127;

    float acc = b3[col];
#pragma unroll
    for (int k = 0; k < F; k++) acc += ps[r * F + k] * Ws[k * D + col];

    const float h = fmaxf(acc, 0.f);
    const size_t o = (size_t)(row0 + r) * D + col;
    out[o] = fmaxf(h + x[o], 0.f);
}

// ---------------------------------------------------------------------------
extern "C" void kernel_launch(void* const* d_in, const int* in_sizes, int n_in,
                              void* d_out, int out_size)
{
    const float* x   = (const float*)d_in[0];
    const float* adj = (const float*)d_in[1];
    const float* W1  = (const float*)d_in[2];
    const float* b1  = (const float*)d_in[3];
    const float* W2  = (const float*)d_in[4];
    const float* b2  = (const float*)d_in[5];
    const float* W3  = (const float*)d_in[6];
    const float* b3  = (const float*)d_in[7];
    float* out = (float*)d_out;

    float *T, *H, *P;
    cudaGetSymbolAddress((void**)&T, g_bufT);
    cudaGetSymbolAddress((void**)&H, g_bufH);
    cudaGetSymbolAddress((void**)&P, g_part);

    const dim3 SPMM_GRID(NSTRIP_GROUPS, SPLIT);      // 79 x 20 blocks, 256 thr
    const int  RED_GRID = (NROWS * F + 255) / 256;   // 782

    // tiled fp16 copy of adj
    convert_kernel<<<2960, 256>>>(adj);
    // T1 = x @ W1
    xw_kernel<D><<<NROWS / 8, 256>>>(x, W1, T);
    // H1 = relu(adj @ T1 + b1)
    spmm_part_kernel<<<SPMM_GRID, 256>>>(T, P);
    reduce_kernel<<<RED_GRID, 256>>>(P, b1, H);
    // T2 = H1 @ W2
    xw_kernel<F><<<NROWS / 8, 256>>>(H, W2, T);
    // H2 = relu(adj @ T2 + b2)
    spmm_part_kernel<<<SPMM_GRID, 256>>>(T, P);
    reduce_kernel<<<RED_GRID, 256>>>(P, b2, H);
    // P = partials of adj @ H2
    spmm_part_kernel<<<SPMM_GRID, 256>>>(H, P);
    // out = relu(relu(sum(P) @ W3 + b3) + x)
    final_kernel<<<NROWS / 2, 256>>>(P, W3, b3, x, out);
}

// round 11
// speedup vs baseline: 1.7917x; 1.0018x over previous
#include <cuda_runtime.h>
#include <cuda_fp16.h>
#include <cstdint>

// Problem constants
#define NROWS 10000
#define KDIM  10000
#define KH    10240     // fp16 adj padded cols (zeros beyond 10000)
#define F     20        // hidden width
#define D     128      // in/out width
#define NSTRIPS ((NROWS + 15) / 16)   // 625 (exact)

// K-split over the padded fp16 matrix: 20 slabs of 512 cols (32 | 512)
#define SPLIT  20
#define SLAB   512
#define SSTEPS (SLAB / 32)      // 16 supersteps (2 fp16 MMAs x 3 n-tiles each)
#define TILE_HALVES (16 * SLAB) // 8192 halves = 16 KB per (strip,slab) tile
#define STRIPS_PER_BLK 8
#define NSTRIP_GROUPS ((NSTRIPS + STRIPS_PER_BLK - 1) / STRIPS_PER_BLK)  // 79
#define PF 4                    // A-load ring depth (supersteps)

// Intra-tile offsets IN HALVES:
#define OFF_TIG   8
#define OFF_GID   32
#define OFF_HALF  256
#define OFF_SS    512

// B smem: half2 words, [kpair 256][col stride 22] -> conflict-free LDS
// (bank = 24*tig + gid + uniform, distinct across all 32 lanes)
#define NSTRIDE 22
#define TS_WORDS (256 * NSTRIDE + 32)

// Scratch (no allocations allowed)
__device__ float  g_bufT[NROWS * F];
__device__ float  g_bufH[NROWS * F];
__device__ float  g_part[SPLIT * NROWS * F];        // 16 MB partials
// Tiled fp16 adj: [strip 625][slab 20][ss 16][half 2][gid 8][tig 4][8 halves]
__device__ __half g_adjh[(size_t)NROWS * KH];       // 204.8 MB

// ---------------------------------------------------------------------------
// Convert adj (fp32, row-major) -> g_adjh (fp16, warp-tiled layout).
// Tile (strip, slab) holds rows [16*strip,16*strip+16) x cols [512*slab, ...).
// Internal order [ss][half][gid][tig][8 halves]: spmm's warp fetch for a
// superstep is 512 B contiguous with per-lane offset = lane*16 B.
// ---------------------------------------------------------------------------
__global__ void __launch_bounds__(256)
convert_kernel(const float* __restrict__ adj)
{
    const size_t total = (size_t)NROWS * (KH / 8);   // thread-ops of 8 cols
    for (size_t i = (size_t)blockIdx.x * 256 + threadIdx.x; i < total;
         i += (size_t)gridDim.x * 256) {
        const int r  = (int)(i / (KH / 8));
        const int c8 = (int)(i % (KH / 8));
        const int c  = c8 * 8;               // padded col of first element

        const int strip = r >> 4;
        const int slab  = c / SLAB;
        const int cs    = c % SLAB;
        const int ss    = cs >> 5;
        const int tig   = (cs & 31) >> 3;
        const int half  = (r & 15) >> 3;
        const int gid   = r & 7;
        __half* dst = g_adjh
            + ((size_t)strip * SPLIT + slab) * TILE_HALVES
            + ss * OFF_SS + half * OFF_HALF + gid * OFF_GID + tig * OFF_TIG;

        if (c < KDIM) {
            const float4* src = (const float4*)(adj + (size_t)r * KDIM + c);
            float4 v0 = src[0], v1 = src[1];
            __half2 h0 = __floats2half2_rn(v0.x, v0.y);
            __half2 h1 = __floats2half2_rn(v0.z, v0.w);
            __half2 h2 = __floats2half2_rn(v1.x, v1.y);
            __half2 h3 = __floats2half2_rn(v1.z, v1.w);
            uint4 w;
            w.x = *(uint32_t*)&h0; w.y = *(uint32_t*)&h1;
            w.z = *(uint32_t*)&h2; w.w = *(uint32_t*)&h3;
            *(uint4*)dst = w;
        } else {
            *(uint4*)dst = make_uint4(0, 0, 0, 0);
        }
    }
}

// ---------------------------------------------------------------------------
// Big GEMM partial (fp16 m16n8k16): part[slab][N,20] = adj[:,slab]@T[slab,20]
// Per-warp 16-row strip over one 512-col slab; 8 warps/block share B staging.
// A: per superstep TWO 512-B contiguous lane-linear fetches feed 2 MMAs x 3
// n-tiles directly as half2 regs (no conversion).
// k-bijection per superstep ss, MMA m (m=0,1), same for A and B:
//   A-slot pair (2tig,2tig+1)   <-> stored halves (8tig+4m, 8tig+4m+1)
//   A-slot pair (2tig+8,2tig+9) <-> stored halves (8tig+4m+2, 8tig+4m+3)
// B staged as half2 Bs[kpair][col] (kpair = global k / 2) at word stride 22.
// Garbage (cols 20/21 + row overhang) only feeds discarded D cols 20..23.
// D/C fragment layout identical to the old m16n8k8 path -> same epilogue.
// ---------------------------------------------------------------------------
__global__ void __launch_bounds__(256)
spmm_part_kernel(const float* __restrict__ T,
                 float* __restrict__ part)
{
    __shared__ uint32_t Ts[TS_WORDS];   // half2 words

    const int tid  = threadIdx.x;
    const int warp = tid >> 5;
    const int lane = tid & 31;
    const int gid  = lane >> 2;   // 0..7  (row-in-group / B col)
    const int tig  = lane & 3;    // 0..3  (k selector)
    const int tig2 = 2 * tig;

    if (tid < 32) Ts[256 * NSTRIDE + tid] = 0;   // pad for overhang reads

    const int strip  = blockIdx.x * STRIPS_PER_BLK + warp;
    const bool active = (strip < NSTRIPS);
    const int strip_c = active ? strip : (NSTRIPS - 1);   // clamp pointers
    const int m0   = strip * 16;
    const int slab = blockIdx.y;

    const __half* tile = g_adjh
        + ((size_t)strip_c * SPLIT + slab) * TILE_HALVES
        + lane * OFF_TIG;                  // lane-linear base (16 B per lane)

    // stage B slab as fp16 half2 pairs: Ts[kp*22+col] = (T[2kp][col], T[2kp+1][col])
    {
        const float* src = T + (size_t)slab * SLAB * F;
#pragma unroll
        for (int it = 0; it < (256 * F) / 256; ++it) {   // 20 iters
            const int i  = it * 256 + tid;               // 0..5119
            const int kp  = i / F;
            const int col = i % F;
            const float f0 = src[kp * 40 + col];        // k = 2kp
            const float f1 = src[kp * 40 + 20 + col];   // k = 2kp+1
            __half2 h = __floats2half2_rn(f0, f1);      // lo = even k
            Ts[kp * NSTRIDE + col] = *(uint32_t*)&h;
        }
    }

    float acc[3][4];
#pragma unroll
    for (int t = 0; t < 3; t++)
#pragma unroll
        for (int j = 0; j < 4; j++) acc[t][j] = 0.0f;

    // A-load register ring (PF supersteps deep; uint4 = 8 halves per half-row)
    uint4 ra[PF], rb[PF];
#pragma unroll
    for (int p = 0; p < PF; p++) {
        ra[p] = *(const uint4*)(tile + p * OFF_SS);
        rb[p] = *(const uint4*)(tile + p * OFF_SS + OFF_HALF);
    }

    __syncthreads();   // staging visible to all warps

    if (active) {
#pragma unroll 4
        for (int ss = 0; ss < SSTEPS; ++ss) {
            const int slot = ss & (PF - 1);

            const uint4 va = ra[slot];   // rows gid,  halves 8tig..8tig+7
            const uint4 vb = rb[slot];   // rows gid+8

            // prefetch superstep ss+PF (tail re-reads a dummy in-bounds spot)
            {
                const int nss = ss + PF;
                const int po  = (nss < SSTEPS) ? nss * OFF_SS : 0;
                ra[slot] = *(const uint4*)(tile + po);
                rb[slot] = *(const uint4*)(tile + po + OFF_HALF);
            }

            const int kpbase = (16 * ss + 4 * tig) * NSTRIDE;

#pragma unroll
            for (int m = 0; m < 2; m++) {
                const uint32_t a0 = (m == 0) ? va.x : va.z;
                const uint32_t a1 = (m == 0) ? vb.x : vb.z;
                const uint32_t a2 = (m == 0) ? va.y : va.w;
                const uint32_t a3 = (m == 0) ? vb.y : vb.w;
                const int r0 = kpbase + 2 * m * NSTRIDE;
#pragma unroll
                for (int t = 0; t < 3; t++) {
                    const int cn = 8 * t + gid;
                    const uint32_t b0 = Ts[r0 + cn];            // k, k+1
                    const uint32_t b1 = Ts[r0 + NSTRIDE + cn];  // k+2, k+3
                    asm volatile(
                        "mma.sync.aligned.m16n8k16.row.col.f32.f16.f16.f32 "
                        "{%0,%1,%2,%3},{%4,%5,%6,%7},{%8,%9},{%0,%1,%2,%3};"
                        : "+f"(acc[t][0]), "+f"(acc[t][1]),
                          "+f"(acc[t][2]), "+f"(acc[t][3])
                        : "r"(a0), "r"(a1), "r"(a2), "r"(a3),
                          "r"(b0), "r"(b1));
                }
            }
        }

        float* po = part + (size_t)slab * NROWS * F;
#pragma unroll
        for (int t = 0; t < 3; t++) {
            const int c = 8 * t + tig2;   // col pairs never straddle 20
            if (c < F) {
                const int r0 = m0 + gid;
                const int r1 = r0 + 8;
                *(float2*)(po + (size_t)r0 * F + c) =
                    make_float2(acc[t][0], acc[t][1]);
                *(float2*)(po + (size_t)r1 * F + c) =
                    make_float2(acc[t][2], acc[t][3]);
            }
        }
    }
}

// ---------------------------------------------------------------------------
// Reduce partials (float4): out[i] = relu( sum_s part[s][i] + bias[i%20] )
// ---------------------------------------------------------------------------
__global__ void __launch_bounds__(256)
reduce_kernel(const float* __restrict__ part, const float* __restrict__ bias,
              float* __restrict__ out)
{
    const int i4 = (blockIdx.x * 256 + threadIdx.x) * 4;
    if (i4 < NROWS * F) {
        float4 s = make_float4(0.f, 0.f, 0.f, 0.f);
#pragma unroll
        for (int sl = 0; sl < SPLIT; sl++) {
            const float4 v = *(const float4*)(part + (size_t)sl * NROWS * F + i4);
            s.x += v.x; s.y += v.y; s.z += v.z; s.w += v.w;
        }
        float4 o;
        o.x = fmaxf(s.x + bias[(i4 + 0) % F], 0.f);
        o.y = fmaxf(s.y + bias[(i4 + 1) % F], 0.f);
        o.z = fmaxf(s.z + bias[(i4 + 2) % F], 0.f);
        o.w = fmaxf(s.w + bias[(i4 + 3) % F], 0.f);
        *(float4*)(out + i4) = o;
    }
}

// ---------------------------------------------------------------------------
// Small GEMM: T[N,20] = Hin[N,KK] @ W[KK,20].  Warp per row, lane = out col.
// ---------------------------------------------------------------------------
template <int KK>
__global__ void __launch_bounds__(256)
xw_kernel(const float* __restrict__ Hin, const float* __restrict__ W,
          float* __restrict__ T)
{
    __shared__ float Ws[KK * F];
    const int tid = threadIdx.x;
    for (int i = tid; i < KK * F; i += 256) Ws[i] = W[i];
    __syncthreads();

    const int warp = tid >> 5;
    const int lane = tid & 31;
    const int row  = blockIdx.x * 8 + warp;   // grid*8 == NROWS exactly

    const float* h = Hin + (size_t)row * KK;
    if (lane < F) {
        float a0 = 0.f, a1 = 0.f, a2 = 0.f, a3 = 0.f;
#pragma unroll 4
        for (int k = 0; k < KK; k += 4) {
            a0 += h[k + 0] * Ws[(k + 0) * F + lane];
            a1 += h[k + 1] * Ws[(k + 1) * F + lane];
            a2 += h[k + 2] * Ws[(k + 2) * F + lane];
            a3 += h[k + 3] * Ws[(k + 3) * F + lane];
        }
        T[(size_t)row * F + lane] = (a0 + a1) + (a2 + a3);
    }
}

// ---------------------------------------------------------------------------
// Final (fused partial-reduce): out = relu( relu((sum_s P_s) @ W3 + b3) + x )
// ---------------------------------------------------------------------------
__global__ void __launch_bounds__(256)
final_kernel(const float* __restrict__ P, const float* __restrict__ W3,
             const float* __restrict__ b3, const float* __restrict__ x,
             float* __restrict__ out)
{
    __shared__ float Ws[F * D];    // 20 x 128
    __shared__ float ps[2 * F];    // reduced P rows for this block
    const int tid = threadIdx.x;
    for (int i = tid; i < F * D; i += 256) Ws[i] = W3[i];

    const int row0 = blockIdx.x * 2;
    if (tid < 2 * F) {
        const int r = tid / F, c = tid % F;
        float s = 0.f;
#pragma unroll
        for (int sl = 0; sl < SPLIT; sl++)
            s += P[(size_t)sl * NROWS * F + (size_t)(row0 + r) * F + c];
        ps[tid] = s;
    }
    __syncthreads();

    const int r   = tid >> 7;
    const int col = tid & 127;

    float acc = b3[col];
#pragma unroll
    for (int k = 0; k < F; k++) acc += ps[r * F + k] * Ws[k * D + col];

    const float h = fmaxf(acc, 0.f);
    const size_t o = (size_t)(row0 + r) * D + col;
    out[o] = fmaxf(h + x[o], 0.f);
}

// ---------------------------------------------------------------------------
extern "C" void kernel_launch(void* const* d_in, const int* in_sizes, int n_in,
                              void* d_out, int out_size)
{
    const float* x   = (const float*)d_in[0];
    const float* adj = (const float*)d_in[1];
    const float* W1  = (const float*)d_in[2];
    const float* b1  = (const float*)d_in[3];
    const float* W2  = (const float*)d_in[4];
    const float* b2  = (const float*)d_in[5];
    const float* W3  = (const float*)d_in[6];
    const float* b3  = (const float*)d_in[7];
    float* out = (float*)d_out;

    float *T, *H, *P;
    cudaGetSymbolAddress((void**)&T, g_bufT);
    cudaGetSymbolAddress((void**)&H, g_bufH);
    cudaGetSymbolAddress((void**)&P, g_part);

    const dim3 SPMM_GRID(NSTRIP_GROUPS, SPLIT);      // 79 x 20 blocks, 256 thr
    const int  RED_GRID = (NROWS * F / 4 + 255) / 256;   // 196

    // tiled fp16 copy of adj
    convert_kernel<<<2960, 256>>>(adj);
    // T1 = x @ W1
    xw_kernel<D><<<NROWS / 8, 256>>>(x, W1, T);
    // H1 = relu(adj @ T1 + b1)
    spmm_part_kernel<<<SPMM_GRID, 256>>>(T, P);
    reduce_kernel<<<RED_GRID, 256>>>(P, b1, H);
    // T2 = H1 @ W2
    xw_kernel<F><<<NROWS / 8, 256>>>(H, W2, T);
    // H2 = relu(adj @ T2 + b2)
    spmm_part_kernel<<<SPMM_GRID, 256>>>(T, P);
    reduce_kernel<<<RED_GRID, 256>>>(P, b2, H);
    // P = partials of adj @ H2
    spmm_part_kernel<<<SPMM_GRID, 256>>>(H, P);
    // out = relu(relu(sum(P) @ W3 + b3) + x)
    final_kernel<<<NROWS / 2, 256>>>(P, W3, b3, x, out);
}

// round 12
// speedup vs baseline: 1.9856x; 1.1082x over previous
#include <cuda_runtime.h>
#include <cuda_fp16.h>
#include <cstdint>

// Problem constants
#define NROWS 10000
#define KDIM  10000
#define KH    10240     // fp16 adj padded cols (zeros beyond 10000)
#define F     20        // hidden width
#define D     128       // in/out width
#define NSTRIPS ((NROWS + 15) / 16)   // 625 (exact)

// K-split over the padded fp16 matrix: 20 slabs of 512 cols (32 | 512)
#define SPLIT  20
#define SLAB   512
#define SSTEPS (SLAB / 32)      // 16 supersteps (2 fp16 MMAs x 3 n-tiles each)
#define TILE_HALVES (16 * SLAB) // 8192 halves = 16 KB per (strip,slab) tile
#define STRIPS_PER_BLK 8
#define NSTRIP_GROUPS ((NSTRIPS + STRIPS_PER_BLK - 1) / STRIPS_PER_BLK)  // 79
#define PF 4                    // fp16 A-load ring depth (supersteps)

// Intra-tile offsets IN HALVES:
#define OFF_TIG   8
#define OFF_GID   32
#define OFF_HALF  256
#define OFF_SS    512

// B smem: half2 words, [kpair 256][col stride 22] -> conflict-free LDS
#define NSTRIDE 22
#define TS_WORDS (256 * NSTRIDE + 32)

// Scratch (no allocations allowed)
__device__ float  g_bufT[NROWS * F];
__device__ float  g_bufH[NROWS * F];
__device__ float  g_part[SPLIT * NROWS * F];        // 16 MB partials
// Tiled fp16 adj: [strip 625][slab 20][ss 16][half 2][gid 8][tig 4][8 halves]
__device__ __half g_adjh[(size_t)NROWS * KH];       // 204.8 MB

__device__ __forceinline__ uint32_t pack_h2(float a, float b) {
    __half2 h = __floats2half2_rn(a, b);
    return *(uint32_t*)&h;
}

// ---------------------------------------------------------------------------
// PASS 0 (fused convert + GEMM): reads fp32 adj, writes tiled fp16 copy,
// computes part[slab][N,20] = adj[:,slab] @ T[slab,20] with fp16 m16n8k16.
// Per superstep each lane loads 8 fp32 cols per half-row (2x float4),
// converts to 8 halves (= the tiled-layout register image), stores the tile
// slot (warp store = 512 B contiguous, lane-linear), and runs the MMAs.
// Pad cols >= KDIM are predicated to zero (and written as zeros to the tile).
// ---------------------------------------------------------------------------
__global__ void __launch_bounds__(256)
spmm_fuse0_kernel(const float* __restrict__ adj,
                  const float* __restrict__ T,
                  float* __restrict__ part)
{
    __shared__ uint32_t Ts[TS_WORDS];   // half2 words

    const int tid  = threadIdx.x;
    const int warp = tid >> 5;
    const int lane = tid & 31;
    const int gid  = lane >> 2;
    const int tig  = lane & 3;
    const int tig2 = 2 * tig;

    if (tid < 32) Ts[256 * NSTRIDE + tid] = 0;

    const int strip  = blockIdx.x * STRIPS_PER_BLK + warp;
    const bool active = (strip < NSTRIPS);
    const int m0   = strip * 16;
    const int slab = blockIdx.y;
    const int cbase = slab * SLAB;       // fp32 col base of this slab

    const float* a_row0 = adj + (size_t)(active ? (m0 + gid) : 0) * KDIM;
    const float* a_row1 = a_row0 + (size_t)8 * KDIM;
    __half* tile_w = g_adjh
        + ((size_t)(active ? strip : 0) * SPLIT + slab) * TILE_HALVES
        + lane * OFF_TIG;               // lane-linear write base

    // stage B slab as fp16 half2 pairs (identical to spmm_part_kernel)
    {
        const float* src = T + (size_t)slab * SLAB * F;
#pragma unroll
        for (int it = 0; it < (256 * F) / 256; ++it) {
            const int i   = it * 256 + tid;
            const int kp  = i / F;
            const int col = i % F;
            Ts[kp * NSTRIDE + col] =
                pack_h2(src[kp * 40 + col], src[kp * 40 + 20 + col]);
        }
    }

    float acc[3][4];
#pragma unroll
    for (int t = 0; t < 3; t++)
#pragma unroll
        for (int j = 0; j < 4; j++) acc[t][j] = 0.0f;

    // fp32 A double-buffer ring (2 supersteps deep)
    float4 r0a[2], r0b[2], r1a[2], r1b[2];
    if (active) {
#pragma unroll
        for (int p = 0; p < 2; p++) {
            const int gc = cbase + 32 * p + 8 * tig;
            const bool v = (gc < KDIM);   // 8-col group wholly valid or not
            r0a[p] = v ? *(const float4*)(a_row0 + gc)     : make_float4(0,0,0,0);
            r0b[p] = v ? *(const float4*)(a_row0 + gc + 4) : make_float4(0,0,0,0);
            r1a[p] = v ? *(const float4*)(a_row1 + gc)     : make_float4(0,0,0,0);
            r1b[p] = v ? *(const float4*)(a_row1 + gc + 4) : make_float4(0,0,0,0);
        }
    }

    __syncthreads();

    if (active) {
#pragma unroll 2
        for (int ss = 0; ss < SSTEPS; ++ss) {
            const int slot = ss & 1;
            const float4 f0a = r0a[slot], f0b = r0b[slot];
            const float4 f1a = r1a[slot], f1b = r1b[slot];

            // prefetch superstep ss+2
            {
                const int nss = ss + 2;
                if (nss < SSTEPS) {
                    const int gc = cbase + 32 * nss + 8 * tig;
                    const bool v = (gc < KDIM);
                    r0a[slot] = v ? *(const float4*)(a_row0 + gc)     : make_float4(0,0,0,0);
                    r0b[slot] = v ? *(const float4*)(a_row0 + gc + 4) : make_float4(0,0,0,0);
                    r1a[slot] = v ? *(const float4*)(a_row1 + gc)     : make_float4(0,0,0,0);
                    r1b[slot] = v ? *(const float4*)(a_row1 + gc + 4) : make_float4(0,0,0,0);
                }
            }

            // convert: va/vb match the tiled layout's register image exactly
            uint4 va, vb;
            va.x = pack_h2(f0a.x, f0a.y); va.y = pack_h2(f0a.z, f0a.w);
            va.z = pack_h2(f0b.x, f0b.y); va.w = pack_h2(f0b.z, f0b.w);
            vb.x = pack_h2(f1a.x, f1a.y); vb.y = pack_h2(f1a.z, f1a.w);
            vb.z = pack_h2(f1b.x, f1b.y); vb.w = pack_h2(f1b.z, f1b.w);

            // tiled fp16 write (warp: 2 x 512 B contiguous, lane-linear)
            *(uint4*)(tile_w + ss * OFF_SS)            = va;
            *(uint4*)(tile_w + ss * OFF_SS + OFF_HALF) = vb;

            const int kpbase = (16 * ss + 4 * tig) * NSTRIDE;
#pragma unroll
            for (int m = 0; m < 2; m++) {
                const uint32_t a0 = (m == 0) ? va.x : va.z;
                const uint32_t a1 = (m == 0) ? vb.x : vb.z;
                const uint32_t a2 = (m == 0) ? va.y : va.w;
                const uint32_t a3 = (m == 0) ? vb.y : vb.w;
                const int r0 = kpbase + 2 * m * NSTRIDE;
#pragma unroll
                for (int t = 0; t < 3; t++) {
                    const int cn = 8 * t + gid;
                    const uint32_t b0 = Ts[r0 + cn];
                    const uint32_t b1 = Ts[r0 + NSTRIDE + cn];
                    asm volatile(
                        "mma.sync.aligned.m16n8k16.row.col.f32.f16.f16.f32 "
                        "{%0,%1,%2,%3},{%4,%5,%6,%7},{%8,%9},{%0,%1,%2,%3};"
                        : "+f"(acc[t][0]), "+f"(acc[t][1]),
                          "+f"(acc[t][2]), "+f"(acc[t][3])
                        : "r"(a0), "r"(a1), "r"(a2), "r"(a3),
                          "r"(b0), "r"(b1));
                }
            }
        }

        float* po = part + (size_t)slab * NROWS * F;
#pragma unroll
        for (int t = 0; t < 3; t++) {
            const int c = 8 * t + tig2;
            if (c < F) {
                const int r0 = m0 + gid;
                const int r1 = r0 + 8;
                *(float2*)(po + (size_t)r0 * F + c) =
                    make_float2(acc[t][0], acc[t][1]);
                *(float2*)(po + (size_t)r1 * F + c) =
                    make_float2(acc[t][2], acc[t][3]);
            }
        }
    }
}

// ---------------------------------------------------------------------------
// Big GEMM partial (fp16 m16n8k16, tiled adj): passes 2 and 3.
// ---------------------------------------------------------------------------
__global__ void __launch_bounds__(256)
spmm_part_kernel(const float* __restrict__ T,
                 float* __restrict__ part)
{
    __shared__ uint32_t Ts[TS_WORDS];

    const int tid  = threadIdx.x;
    const int warp = tid >> 5;
    const int lane = tid & 31;
    const int gid  = lane >> 2;
    const int tig  = lane & 3;
    const int tig2 = 2 * tig;

    if (tid < 32) Ts[256 * NSTRIDE + tid] = 0;

    const int strip  = blockIdx.x * STRIPS_PER_BLK + warp;
    const bool active = (strip < NSTRIPS);
    const int strip_c = active ? strip : (NSTRIPS - 1);
    const int m0   = strip * 16;
    const int slab = blockIdx.y;

    const __half* tile = g_adjh
        + ((size_t)strip_c * SPLIT + slab) * TILE_HALVES
        + lane * OFF_TIG;

    {
        const float* src = T + (size_t)slab * SLAB * F;
#pragma unroll
        for (int it = 0; it < (256 * F) / 256; ++it) {
            const int i   = it * 256 + tid;
            const int kp  = i / F;
            const int col = i % F;
            Ts[kp * NSTRIDE + col] =
                pack_h2(src[kp * 40 + col], src[kp * 40 + 20 + col]);
        }
    }

    float acc[3][4];
#pragma unroll
    for (int t = 0; t < 3; t++)
#pragma unroll
        for (int j = 0; j < 4; j++) acc[t][j] = 0.0f;

    uint4 ra[PF], rb[PF];
#pragma unroll
    for (int p = 0; p < PF; p++) {
        ra[p] = *(const uint4*)(tile + p * OFF_SS);
        rb[p] = *(const uint4*)(tile + p * OFF_SS + OFF_HALF);
    }

    __syncthreads();

    if (active) {
#pragma unroll 4
        for (int ss = 0; ss < SSTEPS; ++ss) {
            const int slot = ss & (PF - 1);
            const uint4 va = ra[slot];
            const uint4 vb = rb[slot];
            {
                const int nss = ss + PF;
                const int po  = (nss < SSTEPS) ? nss * OFF_SS : 0;
                ra[slot] = *(const uint4*)(tile + po);
                rb[slot] = *(const uint4*)(tile + po + OFF_HALF);
            }

            const int kpbase = (16 * ss + 4 * tig) * NSTRIDE;
#pragma unroll
            for (int m = 0; m < 2; m++) {
                const uint32_t a0 = (m == 0) ? va.x : va.z;
                const uint32_t a1 = (m == 0) ? vb.x : vb.z;
                const uint32_t a2 = (m == 0) ? va.y : va.w;
                const uint32_t a3 = (m == 0) ? vb.y : vb.w;
                const int r0 = kpbase + 2 * m * NSTRIDE;
#pragma unroll
                for (int t = 0; t < 3; t++) {
                    const int cn = 8 * t + gid;
                    const uint32_t b0 = Ts[r0 + cn];
                    const uint32_t b1 = Ts[r0 + NSTRIDE + cn];
                    asm volatile(
                        "mma.sync.aligned.m16n8k16.row.col.f32.f16.f16.f32 "
                        "{%0,%1,%2,%3},{%4,%5,%6,%7},{%8,%9},{%0,%1,%2,%3};"
                        : "+f"(acc[t][0]), "+f"(acc[t][1]),
                          "+f"(acc[t][2]), "+f"(acc[t][3])
                        : "r"(a0), "r"(a1), "r"(a2), "r"(a3),
                          "r"(b0), "r"(b1));
                }
            }
        }

        float* po = part + (size_t)slab * NROWS * F;
#pragma unroll
        for (int t = 0; t < 3; t++) {
            const int c = 8 * t + tig2;
            if (c < F) {
                const int r0 = m0 + gid;
                const int r1 = r0 + 8;
                *(float2*)(po + (size_t)r0 * F + c) =
                    make_float2(acc[t][0], acc[t][1]);
                *(float2*)(po + (size_t)r1 * F + c) =
                    make_float2(acc[t][2], acc[t][3]);
            }
        }
    }
}

// ---------------------------------------------------------------------------
// Fused reduce + small GEMM:
//   h[row][:] = relu( sum_s P[s][row][:] + b[:] ),  T[row][:] = h[row][:] @ W
// Warp per row; lane < 20 handles one column.
// ---------------------------------------------------------------------------
__global__ void __launch_bounds__(256)
xwred_kernel(const float* __restrict__ P, const float* __restrict__ bias,
             const float* __restrict__ W, float* __restrict__ T)
{
    __shared__ float Ws[F * F];       // 20 x 20
    __shared__ float hs[8][F];
    const int tid  = threadIdx.x;
    const int warp = tid >> 5;
    const int lane = tid & 31;
    const int row  = blockIdx.x * 8 + warp;   // grid*8 == NROWS

    for (int i = tid; i < F * F; i += 256) Ws[i] = W[i];

    if (lane < F) {
        float s = 0.f;
#pragma unroll
        for (int sl = 0; sl < SPLIT; sl++)
            s += P[(size_t)sl * NROWS * F + (size_t)row * F + lane];
        hs[warp][lane] = fmaxf(s + bias[lane], 0.f);
    }
    __syncthreads();   // Ws staged + hs visible

    if (lane < F) {
        float t = 0.f;
#pragma unroll
        for (int k = 0; k < F; k++) t += hs[warp][k] * Ws[k * F + lane];
        T[(size_t)row * F + lane] = t;
    }
}

// ---------------------------------------------------------------------------
// Reduce partials (float4): out[i] = relu( sum_s part[s][i] + bias[i%20] )
// ---------------------------------------------------------------------------
__global__ void __launch_bounds__(256)
reduce_kernel(const float* __restrict__ part, const float* __restrict__ bias,
              float* __restrict__ out)
{
    const int i4 = (blockIdx.x * 256 + threadIdx.x) * 4;
    if (i4 < NROWS * F) {
        float4 s = make_float4(0.f, 0.f, 0.f, 0.f);
#pragma unroll
        for (int sl = 0; sl < SPLIT; sl++) {
            const float4 v = *(const float4*)(part + (size_t)sl * NROWS * F + i4);
            s.x += v.x; s.y += v.y; s.z += v.z; s.w += v.w;
        }
        float4 o;
        o.x = fmaxf(s.x + bias[(i4 + 0) % F], 0.f);
        o.y = fmaxf(s.y + bias[(i4 + 1) % F], 0.f);
        o.z = fmaxf(s.z + bias[(i4 + 2) % F], 0.f);
        o.w = fmaxf(s.w + bias[(i4 + 3) % F], 0.f);
        *(float4*)(out + i4) = o;
    }
}

// ---------------------------------------------------------------------------
// Small GEMM: T[N,20] = Hin[N,KK] @ W[KK,20].  Warp per row, lane = out col.
// ---------------------------------------------------------------------------
template <int KK>
__global__ void __launch_bounds__(256)
xw_kernel(const float* __restrict__ Hin, const float* __restrict__ W,
          float* __restrict__ T)
{
    __shared__ float Ws[KK * F];
    const int tid = threadIdx.x;
    for (int i = tid; i < KK * F; i += 256) Ws[i] = W[i];
    __syncthreads();

    const int warp = tid >> 5;
    const int lane = tid & 31;
    const int row  = blockIdx.x * 8 + warp;

    const float* h = Hin + (size_t)row * KK;
    if (lane < F) {
        float a0 = 0.f, a1 = 0.f, a2 = 0.f, a3 = 0.f;
#pragma unroll 4
        for (int k = 0; k < KK; k += 4) {
            a0 += h[k + 0] * Ws[(k + 0) * F + lane];
            a1 += h[k + 1] * Ws[(k + 1) * F + lane];
            a2 += h[k + 2] * Ws[(k + 2) * F + lane];
            a3 += h[k + 3] * Ws[(k + 3) * F + lane];
        }
        T[(size_t)row * F + lane] = (a0 + a1) + (a2 + a3);
    }
}

// ---------------------------------------------------------------------------
// Final (fused partial-reduce): out = relu( relu((sum_s P_s) @ W3 + b3) + x )
// ---------------------------------------------------------------------------
__global__ void __launch_bounds__(256)
final_kernel(const float* __restrict__ P, const float* __restrict__ W3,
             const float* __restrict__ b3, const float* __restrict__ x,
             float* __restrict__ out)
{
    __shared__ float Ws[F * D];
    __shared__ float ps[2 * F];
    const int tid = threadIdx.x;
    for (int i = tid; i < F * D; i += 256) Ws[i] = W3[i];

    const int row0 = blockIdx.x * 2;
    if (tid < 2 * F) {
        const int r = tid / F, c = tid % F;
        float s = 0.f;
#pragma unroll
        for (int sl = 0; sl < SPLIT; sl++)
            s += P[(size_t)sl * NROWS * F + (size_t)(row0 + r) * F + c];
        ps[tid] = s;
    }
    __syncthreads();

    const int r   = tid >> 7;
    const int col = tid & 127;

    float acc = b3[col];
#pragma unroll
    for (int k = 0; k < F; k++) acc += ps[r * F + k] * Ws[k * D + col];

    const float h = fmaxf(acc, 0.f);
    const size_t o = (size_t)(row0 + r) * D + col;
    out[o] = fmaxf(h + x[o], 0.f);
}

// ---------------------------------------------------------------------------
extern "C" void kernel_launch(void* const* d_in, const int* in_sizes, int n_in,
                              void* d_out, int out_size)
{
    const float* x   = (const float*)d_in[0];
    const float* adj = (const float*)d_in[1];
    const float* W1  = (const float*)d_in[2];
    const float* b1  = (const float*)d_in[3];
    const float* W2  = (const float*)d_in[4];
    const float* b2  = (const float*)d_in[5];
    const float* W3  = (const float*)d_in[6];
    const float* b3  = (const float*)d_in[7];
    float* out = (float*)d_out;

    float *T, *H, *P;
    cudaGetSymbolAddress((void**)&T, g_bufT);
    cudaGetSymbolAddress((void**)&H, g_bufH);
    cudaGetSymbolAddress((void**)&P, g_part);

    const dim3 SPMM_GRID(NSTRIP_GROUPS, SPLIT);          // 79 x 20, 256 thr
    const int  RED_GRID = (NROWS * F / 4 + 255) / 256;   // 196

    // T1 = x @ W1
    xw_kernel<D><<<NROWS / 8, 256>>>(x, W1, T);
    // P = partials of adj @ T1; also writes tiled fp16 adj copy
    spmm_fuse0_kernel<<<SPMM_GRID, 256>>>(adj, T, P);
    // T2 = relu(sum(P) + b1) @ W2   (fused reduce + xw)
    xwred_kernel<<<NROWS / 8, 256>>>(P, b1, W2, T);
    // P = partials of adj @ T2  (fp16 tiled adj)
    spmm_part_kernel<<<SPMM_GRID, 256>>>(T, P);
    // H2 = relu(sum(P) + b2)
    reduce_kernel<<<RED_GRID, 256>>>(P, b2, H);
    // P = partials of adj @ H2
    spmm_part_kernel<<<SPMM_GRID, 256>>>(H, P);
    // out = relu(relu(sum(P) @ W3 + b3) + x)
    final_kernel<<<NROWS / 2, 256>>>(P, W3, b3, x, out);
}

// round 13
// speedup vs baseline: 2.0229x; 1.0188x over previous
#include <cuda_runtime.h>
#include <cuda_fp16.h>
#include <cstdint>

// Problem constants
#define NROWS 10000
#define KDIM  10000
#define KH    10240     // fp16 adj padded cols (zeros beyond 10000)
#define F     20        // hidden width
#define D     128       // in/out width
#define NSTRIPS ((NROWS + 15) / 16)   // 625 (exact)

// K-split over the padded fp16 matrix: 20 slabs of 512 cols (32 | 512)
#define SPLIT  20
#define SLAB   512
#define SSTEPS (SLAB / 32)      // 16 supersteps (2 fp16 MMAs x 3 n-tiles each)
#define TILE_HALVES (16 * SLAB) // 8192 halves = 16 KB per (strip,slab) tile
#define STRIPS_PER_BLK 8
#define NSTRIP_GROUPS ((NSTRIPS + STRIPS_PER_BLK - 1) / STRIPS_PER_BLK)  // 79
#define PF 2                    // fp16 A-load ring depth (regs: 16 vs 32)

// Intra-tile offsets IN HALVES:
#define OFF_TIG   8
#define OFF_GID   32
#define OFF_HALF  256
#define OFF_SS    512

// B smem: half2 words, [kpair 256][col stride 22] -> conflict-free LDS
#define NSTRIDE 22
#define TS_WORDS (256 * NSTRIDE + 32)

// Scratch (no allocations allowed)
__device__ float  g_bufT[NROWS * F];
__device__ float  g_bufH[NROWS * F];
__device__ float  g_part[SPLIT * NROWS * F];        // 16 MB partials
// Tiled fp16 adj: [strip 625][slab 20][ss 16][half 2][gid 8][tig 4][8 halves]
__device__ __half g_adjh[(size_t)NROWS * KH];       // 204.8 MB

__device__ __forceinline__ uint32_t pack_h2(float a, float b) {
    __half2 h = __floats2half2_rn(a, b);
    return *(uint32_t*)&h;
}

// ---------------------------------------------------------------------------
// PASS 0 (fused convert + GEMM): reads fp32 adj, writes tiled fp16 copy,
// computes part[slab][N,20] = adj[:,slab] @ T[slab,20] with fp16 m16n8k16.
// ---------------------------------------------------------------------------
__global__ void __launch_bounds__(256, 3)
spmm_fuse0_kernel(const float* __restrict__ adj,
                  const float* __restrict__ T,
                  float* __restrict__ part)
{
    __shared__ uint32_t Ts[TS_WORDS];   // half2 words

    const int tid  = threadIdx.x;
    const int warp = tid >> 5;
    const int lane = tid & 31;
    const int gid  = lane >> 2;
    const int tig  = lane & 3;
    const int tig2 = 2 * tig;

    if (tid < 32) Ts[256 * NSTRIDE + tid] = 0;

    const int strip  = blockIdx.x * STRIPS_PER_BLK + warp;
    const bool active = (strip < NSTRIPS);
    const int m0   = strip * 16;
    const int slab = blockIdx.y;
    const int cbase = slab * SLAB;       // fp32 col base of this slab

    const float* a_row0 = adj + (size_t)(active ? (m0 + gid) : 0) * KDIM;
    const float* a_row1 = a_row0 + (size_t)8 * KDIM;
    __half* tile_w = g_adjh
        + ((size_t)(active ? strip : 0) * SPLIT + slab) * TILE_HALVES
        + lane * OFF_TIG;               // lane-linear write base

    // stage B slab as fp16 half2 pairs
    {
        const float* src = T + (size_t)slab * SLAB * F;
#pragma unroll
        for (int it = 0; it < (256 * F) / 256; ++it) {
            const int i   = it * 256 + tid;
            const int kp  = i / F;
            const int col = i % F;
            Ts[kp * NSTRIDE + col] =
                pack_h2(src[kp * 40 + col], src[kp * 40 + 20 + col]);
        }
    }

    float acc[3][4];
#pragma unroll
    for (int t = 0; t < 3; t++)
#pragma unroll
        for (int j = 0; j < 4; j++) acc[t][j] = 0.0f;

    // fp32 A double-buffer ring (2 supersteps deep)
    float4 r0a[2], r0b[2], r1a[2], r1b[2];
    if (active) {
#pragma unroll
        for (int p = 0; p < 2; p++) {
            const int gc = cbase + 32 * p + 8 * tig;
            const bool v = (gc < KDIM);   // 8-col group wholly valid or not
            r0a[p] = v ? *(const float4*)(a_row0 + gc)     : make_float4(0,0,0,0);
            r0b[p] = v ? *(const float4*)(a_row0 + gc + 4) : make_float4(0,0,0,0);
            r1a[p] = v ? *(const float4*)(a_row1 + gc)     : make_float4(0,0,0,0);
            r1b[p] = v ? *(const float4*)(a_row1 + gc + 4) : make_float4(0,0,0,0);
        }
    }

    __syncthreads();

    if (active) {
#pragma unroll 2
        for (int ss = 0; ss < SSTEPS; ++ss) {
            const int slot = ss & 1;
            const float4 f0a = r0a[slot], f0b = r0b[slot];
            const float4 f1a = r1a[slot], f1b = r1b[slot];

            // prefetch superstep ss+2
            {
                const int nss = ss + 2;
                if (nss < SSTEPS) {
                    const int gc = cbase + 32 * nss + 8 * tig;
                    const bool v = (gc < KDIM);
                    r0a[slot] = v ? *(const float4*)(a_row0 + gc)     : make_float4(0,0,0,0);
                    r0b[slot] = v ? *(const float4*)(a_row0 + gc + 4) : make_float4(0,0,0,0);
                    r1a[slot] = v ? *(const float4*)(a_row1 + gc)     : make_float4(0,0,0,0);
                    r1b[slot] = v ? *(const float4*)(a_row1 + gc + 4) : make_float4(0,0,0,0);
                }
            }

            // convert: va/vb match the tiled layout's register image exactly
            uint4 va, vb;
            va.x = pack_h2(f0a.x, f0a.y); va.y = pack_h2(f0a.z, f0a.w);
            va.z = pack_h2(f0b.x, f0b.y); va.w = pack_h2(f0b.z, f0b.w);
            vb.x = pack_h2(f1a.x, f1a.y); vb.y = pack_h2(f1a.z, f1a.w);
            vb.z = pack_h2(f1b.x, f1b.y); vb.w = pack_h2(f1b.z, f1b.w);

            // tiled fp16 write (warp: 2 x 512 B contiguous, lane-linear)
            *(uint4*)(tile_w + ss * OFF_SS)            = va;
            *(uint4*)(tile_w + ss * OFF_SS + OFF_HALF) = vb;

            const int kpbase = (16 * ss + 4 * tig) * NSTRIDE;
#pragma unroll
            for (int m = 0; m < 2; m++) {
                const uint32_t a0 = (m == 0) ? va.x : va.z;
                const uint32_t a1 = (m == 0) ? vb.x : vb.z;
                const uint32_t a2 = (m == 0) ? va.y : va.w;
                const uint32_t a3 = (m == 0) ? vb.y : vb.w;
                const int r0 = kpbase + 2 * m * NSTRIDE;
#pragma unroll
                for (int t = 0; t < 3; t++) {
                    const int cn = 8 * t + gid;
                    const uint32_t b0 = Ts[r0 + cn];
                    const uint32_t b1 = Ts[r0 + NSTRIDE + cn];
                    asm volatile(
                        "mma.sync.aligned.m16n8k16.row.col.f32.f16.f16.f32 "
                        "{%0,%1,%2,%3},{%4,%5,%6,%7},{%8,%9},{%0,%1,%2,%3};"
                        : "+f"(acc[t][0]), "+f"(acc[t][1]),
                          "+f"(acc[t][2]), "+f"(acc[t][3])
                        : "r"(a0), "r"(a1), "r"(a2), "r"(a3),
                          "r"(b0), "r"(b1));
                }
            }
        }

        float* po = part + (size_t)slab * NROWS * F;
#pragma unroll
        for (int t = 0; t < 3; t++) {
            const int c = 8 * t + tig2;
            if (c < F) {
                const int r0 = m0 + gid;
                const int r1 = r0 + 8;
                *(float2*)(po + (size_t)r0 * F + c) =
                    make_float2(acc[t][0], acc[t][1]);
                *(float2*)(po + (size_t)r1 * F + c) =
                    make_float2(acc[t][2], acc[t][3]);
            }
        }
    }
}

// ---------------------------------------------------------------------------
// Big GEMM partial (fp16 m16n8k16, tiled adj): passes 2 and 3.
// PF=2 ring + launch_bounds(256,4): ~62 regs -> 4 blocks/SM (occ 50%).
// ---------------------------------------------------------------------------
__global__ void __launch_bounds__(256, 4)
spmm_part_kernel(const float* __restrict__ T,
                 float* __restrict__ part)
{
    __shared__ uint32_t Ts[TS_WORDS];

    const int tid  = threadIdx.x;
    const int warp = tid >> 5;
    const int lane = tid & 31;
    const int gid  = lane >> 2;
    const int tig  = lane & 3;
    const int tig2 = 2 * tig;

    if (tid < 32) Ts[256 * NSTRIDE + tid] = 0;

    const int strip  = blockIdx.x * STRIPS_PER_BLK + warp;
    const bool active = (strip < NSTRIPS);
    const int strip_c = active ? strip : (NSTRIPS - 1);
    const int m0   = strip * 16;
    const int slab = blockIdx.y;

    const __half* tile = g_adjh
        + ((size_t)strip_c * SPLIT + slab) * TILE_HALVES
        + lane * OFF_TIG;

    {
        const float* src = T + (size_t)slab * SLAB * F;
#pragma unroll
        for (int it = 0; it < (256 * F) / 256; ++it) {
            const int i   = it * 256 + tid;
            const int kp  = i / F;
            const int col = i % F;
            Ts[kp * NSTRIDE + col] =
                pack_h2(src[kp * 40 + col], src[kp * 40 + 20 + col]);
        }
    }

    float acc[3][4];
#pragma unroll
    for (int t = 0; t < 3; t++)
#pragma unroll
        for (int j = 0; j < 4; j++) acc[t][j] = 0.0f;

    uint4 ra[PF], rb[PF];
#pragma unroll
    for (int p = 0; p < PF; p++) {
        ra[p] = *(const uint4*)(tile + p * OFF_SS);
        rb[p] = *(const uint4*)(tile + p * OFF_SS + OFF_HALF);
    }

    __syncthreads();

    if (active) {
#pragma unroll 4
        for (int ss = 0; ss < SSTEPS; ++ss) {
            const int slot = ss & (PF - 1);
            const uint4 va = ra[slot];
            const uint4 vb = rb[slot];
            {
                const int nss = ss + PF;
                const int po  = (nss < SSTEPS) ? nss * OFF_SS : 0;
                ra[slot] = *(const uint4*)(tile + po);
                rb[slot] = *(const uint4*)(tile + po + OFF_HALF);
            }

            const int kpbase = (16 * ss + 4 * tig) * NSTRIDE;
#pragma unroll
            for (int m = 0; m < 2; m++) {
                const uint32_t a0 = (m == 0) ? va.x : va.z;
                const uint32_t a1 = (m == 0) ? vb.x : vb.z;
                const uint32_t a2 = (m == 0) ? va.y : va.w;
                const uint32_t a3 = (m == 0) ? vb.y : vb.w;
                const int r0 = kpbase + 2 * m * NSTRIDE;
#pragma unroll
                for (int t = 0; t < 3; t++) {
                    const int cn = 8 * t + gid;
                    const uint32_t b0 = Ts[r0 + cn];
                    const uint32_t b1 = Ts[r0 + NSTRIDE + cn];
                    asm volatile(
                        "mma.sync.aligned.m16n8k16.row.col.f32.f16.f16.f32 "
                        "{%0,%1,%2,%3},{%4,%5,%6,%7},{%8,%9},{%0,%1,%2,%3};"
                        : "+f"(acc[t][0]), "+f"(acc[t][1]),
                          "+f"(acc[t][2]), "+f"(acc[t][3])
                        : "r"(a0), "r"(a1), "r"(a2), "r"(a3),
                          "r"(b0), "r"(b1));
                }
            }
        }

        float* po = part + (size_t)slab * NROWS * F;
#pragma unroll
        for (int t = 0; t < 3; t++) {
            const int c = 8 * t + tig2;
            if (c < F) {
                const int r0 = m0 + gid;
                const int r1 = r0 + 8;
                *(float2*)(po + (size_t)r0 * F + c) =
                    make_float2(acc[t][0], acc[t][1]);
                *(float2*)(po + (size_t)r1 * F + c) =
                    make_float2(acc[t][2], acc[t][3]);
            }
        }
    }
}

// ---------------------------------------------------------------------------
// Fused reduce + small GEMM:
//   h[row][:] = relu( sum_s P[s][row][:] + b[:] ),  T[row][:] = h[row][:] @ W
// ---------------------------------------------------------------------------
__global__ void __launch_bounds__(256)
xwred_kernel(const float* __restrict__ P, const float* __restrict__ bias,
             const float* __restrict__ W, float* __restrict__ T)
{
    __shared__ float Ws[F * F];       // 20 x 20
    __shared__ float hs[8][F];
    const int tid  = threadIdx.x;
    const int warp = tid >> 5;
    const int lane = tid & 31;
    const int row  = blockIdx.x * 8 + warp;   // grid*8 == NROWS

    for (int i = tid; i < F * F; i += 256) Ws[i] = W[i];

    if (lane < F) {
        float s = 0.f;
#pragma unroll
        for (int sl = 0; sl < SPLIT; sl++)
            s += P[(size_t)sl * NROWS * F + (size_t)row * F + lane];
        hs[warp][lane] = fmaxf(s + bias[lane], 0.f);
    }
    __syncthreads();   // Ws staged + hs visible

    if (lane < F) {
        float t = 0.f;
#pragma unroll
        for (int k = 0; k < F; k++) t += hs[warp][k] * Ws[k * F + lane];
        T[(size_t)row * F + lane] = t;
    }
}

// ---------------------------------------------------------------------------
// Reduce partials (float4): out[i] = relu( sum_s part[s][i] + bias[i%20] )
// ---------------------------------------------------------------------------
__global__ void __launch_bounds__(256)
reduce_kernel(const float* __restrict__ part, const float* __restrict__ bias,
              float* __restrict__ out)
{
    const int i4 = (blockIdx.x * 256 + threadIdx.x) * 4;
    if (i4 < NROWS * F) {
        float4 s = make_float4(0.f, 0.f, 0.f, 0.f);
#pragma unroll
        for (int sl = 0; sl < SPLIT; sl++) {
            const float4 v = *(const float4*)(part + (size_t)sl * NROWS * F + i4);
            s.x += v.x; s.y += v.y; s.z += v.z; s.w += v.w;
        }
        float4 o;
        o.x = fmaxf(s.x + bias[(i4 + 0) % F], 0.f);
        o.y = fmaxf(s.y + bias[(i4 + 1) % F], 0.f);
        o.z = fmaxf(s.z + bias[(i4 + 2) % F], 0.f);
        o.w = fmaxf(s.w + bias[(i4 + 3) % F], 0.f);
        *(float4*)(out + i4) = o;
    }
}

// ---------------------------------------------------------------------------
// Small GEMM: T[N,20] = Hin[N,KK] @ W[KK,20].  Warp per row, lane = out col.
// ---------------------------------------------------------------------------
template <int KK>
__global__ void __launch_bounds__(256)
xw_kernel(const float* __restrict__ Hin, const float* __restrict__ W,
          float* __restrict__ T)
{
    __shared__ float Ws[KK * F];
    const int tid = threadIdx.x;
    for (int i = tid; i < KK * F; i += 256) Ws[i] = W[i];
    __syncthreads();

    const int warp = tid >> 5;
    const int lane = tid & 31;
    const int row  = blockIdx.x * 8 + warp;

    const float* h = Hin + (size_t)row * KK;
    if (lane < F) {
        float a0 = 0.f, a1 = 0.f, a2 = 0.f, a3 = 0.f;
#pragma unroll 4
        for (int k = 0; k < KK; k += 4) {
            a0 += h[k + 0] * Ws[(k + 0) * F + lane];
            a1 += h[k + 1] * Ws[(k + 1) * F + lane];
            a2 += h[k + 2] * Ws[(k + 2) * F + lane];
            a3 += h[k + 3] * Ws[(k + 3) * F + lane];
        }
        T[(size_t)row * F + lane] = (a0 + a1) + (a2 + a3);
    }
}

// ---------------------------------------------------------------------------
// Final (fused partial-reduce): out = relu( relu((sum_s P_s) @ W3 + b3) + x )
// ---------------------------------------------------------------------------
__global__ void __launch_bounds__(256)
final_kernel(const float* __restrict__ P, const float* __restrict__ W3,
             const float* __restrict__ b3, const float* __restrict__ x,
             float* __restrict__ out)
{
    __shared__ float Ws[F * D];
    __shared__ float ps[2 * F];
    const int tid = threadIdx.x;
    for (int i = tid; i < F * D; i += 256) Ws[i] = W3[i];

    const int row0 = blockIdx.x * 2;
    if (tid < 2 * F) {
        const int r = tid / F, c = tid % F;
        float s = 0.f;
#pragma unroll
        for (int sl = 0; sl < SPLIT; sl++)
            s += P[(size_t)sl * NROWS * F + (size_t)(row0 + r) * F + c];
        ps[tid] = s;
    }
    __syncthreads();

    const int r   = tid >> 7;
    const int col = tid & 127;

    float acc = b3[col];
#pragma unroll
    for (int k = 0; k < F; k++) acc += ps[r * F + k] * Ws[k * D + col];

    const float h = fmaxf(acc, 0.f);
    const size_t o = (size_t)(row0 + r) * D + col;
    out[o] = fmaxf(h + x[o], 0.f);
}

// ---------------------------------------------------------------------------
extern "C" void kernel_launch(void* const* d_in, const int* in_sizes, int n_in,
                              void* d_out, int out_size)
{
    const float* x   = (const float*)d_in[0];
    const float* adj = (const float*)d_in[1];
    const float* W1  = (const float*)d_in[2];
    const float* b1  = (const float*)d_in[3];
    const float* W2  = (const float*)d_in[4];
    const float* b2  = (const float*)d_in[5];
    const float* W3  = (const float*)d_in[6];
    const float* b3  = (const float*)d_in[7];
    float* out = (float*)d_out;

    float *T, *H, *P;
    cudaGetSymbolAddress((void**)&T, g_bufT);
    cudaGetSymbolAddress((void**)&H, g_bufH);
    cudaGetSymbolAddress((void**)&P, g_part);

    const dim3 SPMM_GRID(NSTRIP_GROUPS, SPLIT);          // 79 x 20, 256 thr
    const int  RED_GRID = (NROWS * F / 4 + 255) / 256;   // 196

    // T1 = x @ W1
    xw_kernel<D><<<NROWS / 8, 256>>>(x, W1, T);
    // P = partials of adj @ T1; also writes tiled fp16 adj copy
    spmm_fuse0_kernel<<<SPMM_GRID, 256>>>(adj, T, P);
    // T2 = relu(sum(P) + b1) @ W2   (fused reduce + xw)
    xwred_kernel<<<NROWS / 8, 256>>>(P, b1, W2, T);
    // P = partials of adj @ T2  (fp16 tiled adj)
    spmm_part_kernel<<<SPMM_GRID, 256>>>(T, P);
    // H2 = relu(sum(P) + b2)
    reduce_kernel<<<RED_GRID, 256>>>(P, b2, H);
    // P = partials of adj @ H2
    spmm_part_kernel<<<SPMM_GRID, 256>>>(H, P);
    // out = relu(relu(sum(P) @ W3 + b3) + x)
    final_kernel<<<NROWS / 2, 256>>>(P, W3, b3, x, out);
}

// round 14
// speedup vs baseline: 2.0593x; 1.0180x over previous
#include <cuda_runtime.h>
#include <cuda_fp16.h>
#include <cstdint>

// Problem constants
#define NROWS 10000
#define KDIM  10000
#define KH    10240     // fp16 adj padded cols (zeros beyond 10000)
#define F     20        // hidden width
#define D     128       // in/out width
#define NSTRIPS ((NROWS + 15) / 16)   // 625 (exact)

// K-split over the padded fp16 matrix: 20 slabs of 512 cols (32 | 512)
#define SPLIT  20
#define SLAB   512
#define SSTEPS (SLAB / 32)      // 16 supersteps (2 fp16 MMAs x 3 n-tiles each)
#define TILE_HALVES (16 * SLAB) // 8192 halves = 16 KB per (strip,slab) tile
#define STRIPS_PER_BLK 8
#define NSTRIP_GROUPS ((NSTRIPS + STRIPS_PER_BLK - 1) / STRIPS_PER_BLK)  // 79
#define ASTAGES 3               // cp.async A pipeline depth

// Intra-tile offsets IN HALVES:
#define OFF_TIG   8
#define OFF_GID   32
#define OFF_HALF  256
#define OFF_SS    512

// B smem: half2 words, [kpair 256][col stride 22] -> conflict-free LDS
#define NSTRIDE 22
#define TS_WORDS (256 * NSTRIDE + 32)

// Scratch (no allocations allowed)
__device__ float  g_bufT[NROWS * F];
__device__ float  g_bufH[NROWS * F];
__device__ float  g_part[SPLIT * NROWS * F];        // 16 MB partials
// Tiled fp16 adj: [strip 625][slab 20][ss 16][half 2][gid 8][tig 4][8 halves]
__device__ __half g_adjh[(size_t)NROWS * KH];       // 204.8 MB

__device__ __forceinline__ uint32_t pack_h2(float a, float b) {
    __half2 h = __floats2half2_rn(a, b);
    return *(uint32_t*)&h;
}
__device__ __forceinline__ uint32_t smem_u32(const void* p) {
    return (uint32_t)__cvta_generic_to_shared(p);
}
__device__ __forceinline__ void cpa16(uint32_t saddr, const void* gptr) {
    asm volatile("cp.async.cg.shared.global [%0], [%1], 16;"
                 :: "r"(saddr), "l"(gptr));
}

// ---------------------------------------------------------------------------
// PASS 0 (fused convert + GEMM): reads fp32 adj, writes tiled fp16 copy,
// computes part[slab][N,20] = adj[:,slab] @ T[slab,20] with fp16 m16n8k16.
// (Unchanged from round 13 — single-variable test isolates the cp.async
// pipeline in spmm_part this round.)
// ---------------------------------------------------------------------------
__global__ void __launch_bounds__(256, 3)
spmm_fuse0_kernel(const float* __restrict__ adj,
                  const float* __restrict__ T,
                  float* __restrict__ part)
{
    __shared__ uint32_t Ts[TS_WORDS];   // half2 words

    const int tid  = threadIdx.x;
    const int warp = tid >> 5;
    const int lane = tid & 31;
    const int gid  = lane >> 2;
    const int tig  = lane & 3;
    const int tig2 = 2 * tig;

    if (tid < 32) Ts[256 * NSTRIDE + tid] = 0;

    const int strip  = blockIdx.x * STRIPS_PER_BLK + warp;
    const bool active = (strip < NSTRIPS);
    const int m0   = strip * 16;
    const int slab = blockIdx.y;
    const int cbase = slab * SLAB;       // fp32 col base of this slab

    const float* a_row0 = adj + (size_t)(active ? (m0 + gid) : 0) * KDIM;
    const float* a_row1 = a_row0 + (size_t)8 * KDIM;
    __half* tile_w = g_adjh
        + ((size_t)(active ? strip : 0) * SPLIT + slab) * TILE_HALVES
        + lane * OFF_TIG;               // lane-linear write base

    // stage B slab as fp16 half2 pairs
    {
        const float* src = T + (size_t)slab * SLAB * F;
#pragma unroll
        for (int it = 0; it < (256 * F) / 256; ++it) {
            const int i   = it * 256 + tid;
            const int kp  = i / F;
            const int col = i % F;
            Ts[kp * NSTRIDE + col] =
                pack_h2(src[kp * 40 + col], src[kp * 40 + 20 + col]);
        }
    }

    float acc[3][4];
#pragma unroll
    for (int t = 0; t < 3; t++)
#pragma unroll
        for (int j = 0; j < 4; j++) acc[t][j] = 0.0f;

    // fp32 A double-buffer ring (2 supersteps deep)
    float4 r0a[2], r0b[2], r1a[2], r1b[2];
    if (active) {
#pragma unroll
        for (int p = 0; p < 2; p++) {
            const int gc = cbase + 32 * p + 8 * tig;
            const bool v = (gc < KDIM);   // 8-col group wholly valid or not
            r0a[p] = v ? *(const float4*)(a_row0 + gc)     : make_float4(0,0,0,0);
            r0b[p] = v ? *(const float4*)(a_row0 + gc + 4) : make_float4(0,0,0,0);
            r1a[p] = v ? *(const float4*)(a_row1 + gc)     : make_float4(0,0,0,0);
            r1b[p] = v ? *(const float4*)(a_row1 + gc + 4) : make_float4(0,0,0,0);
        }
    }

    __syncthreads();

    if (active) {
#pragma unroll 2
        for (int ss = 0; ss < SSTEPS; ++ss) {
            const int slot = ss & 1;
            const float4 f0a = r0a[slot], f0b = r0b[slot];
            const float4 f1a = r1a[slot], f1b = r1b[slot];

            // prefetch superstep ss+2
            {
                const int nss = ss + 2;
                if (nss < SSTEPS) {
                    const int gc = cbase + 32 * nss + 8 * tig;
                    const bool v = (gc < KDIM);
                    r0a[slot] = v ? *(const float4*)(a_row0 + gc)     : make_float4(0,0,0,0);
                    r0b[slot] = v ? *(const float4*)(a_row0 + gc + 4) : make_float4(0,0,0,0);
                    r1a[slot] = v ? *(const float4*)(a_row1 + gc)     : make_float4(0,0,0,0);
                    r1b[slot] = v ? *(const float4*)(a_row1 + gc + 4) : make_float4(0,0,0,0);
                }
            }

            // convert: va/vb match the tiled layout's register image exactly
            uint4 va, vb;
            va.x = pack_h2(f0a.x, f0a.y); va.y = pack_h2(f0a.z, f0a.w);
            va.z = pack_h2(f0b.x, f0b.y); va.w = pack_h2(f0b.z, f0b.w);
            vb.x = pack_h2(f1a.x, f1a.y); vb.y = pack_h2(f1a.z, f1a.w);
            vb.z = pack_h2(f1b.x, f1b.y); vb.w = pack_h2(f1b.z, f1b.w);

            // tiled fp16 write (warp: 2 x 512 B contiguous, lane-linear)
            *(uint4*)(tile_w + ss * OFF_SS)            = va;
            *(uint4*)(tile_w + ss * OFF_SS + OFF_HALF) = vb;

            const int kpbase = (16 * ss + 4 * tig) * NSTRIDE;
#pragma unroll
            for (int m = 0; m < 2; m++) {
                const uint32_t a0 = (m == 0) ? va.x : va.z;
                const uint32_t a1 = (m == 0) ? vb.x : vb.z;
                const uint32_t a2 = (m == 0) ? va.y : va.w;
                const uint32_t a3 = (m == 0) ? vb.y : vb.w;
                const int r0 = kpbase + 2 * m * NSTRIDE;
#pragma unroll
                for (int t = 0; t < 3; t++) {
                    const int cn = 8 * t + gid;
                    const uint32_t b0 = Ts[r0 + cn];
                    const uint32_t b1 = Ts[r0 + NSTRIDE + cn];
                    asm volatile(
                        "mma.sync.aligned.m16n8k16.row.col.f32.f16.f16.f32 "
                        "{%0,%1,%2,%3},{%4,%5,%6,%7},{%8,%9},{%0,%1,%2,%3};"
                        : "+f"(acc[t][0]), "+f"(acc[t][1]),
                          "+f"(acc[t][2]), "+f"(acc[t][3])
                        : "r"(a0), "r"(a1), "r"(a2), "r"(a3),
                          "r"(b0), "r"(b1));
                }
            }
        }

        float* po = part + (size_t)slab * NROWS * F;
#pragma unroll
        for (int t = 0; t < 3; t++) {
            const int c = 8 * t + tig2;
            if (c < F) {
                const int r0 = m0 + gid;
                const int r1 = r0 + 8;
                *(float2*)(po + (size_t)r0 * F + c) =
                    make_float2(acc[t][0], acc[t][1]);
                *(float2*)(po + (size_t)r1 * F + c) =
                    make_float2(acc[t][2], acc[t][3]);
            }
        }
    }
}

// ---------------------------------------------------------------------------
// Big GEMM partial (fp16 m16n8k16, tiled adj): passes 2 and 3.
// A path: per-warp 3-stage cp.async pipeline into smem. Each lane copies the
// exact 16 B it will consume (lane-linear both sides) -> synchronization is
// cp.async.wait_group alone, no barrier, no ring registers. Depth 3 + 4
// blocks/SM simultaneously (previously mutually exclusive via regs).
// ---------------------------------------------------------------------------
__global__ void __launch_bounds__(256, 4)
spmm_part_kernel(const float* __restrict__ T,
                 float* __restrict__ part)
{
    __shared__ uint32_t Ts[TS_WORDS];
    __shared__ __align__(16) __half As[STRIPS_PER_BLK][ASTAGES][512]; // 24 KB

    const int tid  = threadIdx.x;
    const int warp = tid >> 5;
    const int lane = tid & 31;
    const int gid  = lane >> 2;
    const int tig  = lane & 3;
    const int tig2 = 2 * tig;

    if (tid < 32) Ts[256 * NSTRIDE + tid] = 0;

    const int strip  = blockIdx.x * STRIPS_PER_BLK + warp;
    const bool active = (strip < NSTRIPS);
    const int strip_c = active ? strip : (NSTRIPS - 1);
    const int m0   = strip * 16;
    const int slab = blockIdx.y;

    const __half* tile = g_adjh
        + ((size_t)strip_c * SPLIT + slab) * TILE_HALVES
        + lane * OFF_TIG;                     // lane-linear global base

    const uint32_t asw = smem_u32(&As[warp][0][0]);  // warp's stage base

    // prologue: fill all ASTAGES stages (issue BEFORE B staging so the
    // A-stream is in flight while we stage B)
#pragma unroll
    for (int p = 0; p < ASTAGES; p++) {
        cpa16(asw + p * 1024 + lane * 16,       tile + p * OFF_SS);
        cpa16(asw + p * 1024 + 512 + lane * 16, tile + p * OFF_SS + OFF_HALF);
        asm volatile("cp.async.commit_group;");
    }

    // stage B slab as fp16 half2 pairs
    {
        const float* src = T + (size_t)slab * SLAB * F;
#pragma unroll
        for (int it = 0; it < (256 * F) / 256; ++it) {
            const int i   = it * 256 + tid;
            const int kp  = i / F;
            const int col = i % F;
            Ts[kp * NSTRIDE + col] =
                pack_h2(src[kp * 40 + col], src[kp * 40 + 20 + col]);
        }
    }

    float acc[3][4];
#pragma unroll
    for (int t = 0; t < 3; t++)
#pragma unroll
        for (int j = 0; j < 4; j++) acc[t][j] = 0.0f;

    __syncthreads();   // B staging visible to all warps

    if (active) {
#pragma unroll
        for (int ss = 0; ss < SSTEPS; ++ss) {
            const int buf = ss % ASTAGES;      // compile-time (full unroll)

            // stage ss is complete once <= ASTAGES-1 groups remain pending
            asm volatile("cp.async.wait_group %0;" :: "n"(ASTAGES - 1));

            // consume own 16-B slots (written by this same lane)
            const uint4 va = *(const uint4*)&As[warp][buf][lane * 8];
            const uint4 vb = *(const uint4*)&As[warp][buf][256 + lane * 8];

            // refill this buffer with stage ss+ASTAGES (LDS above already
            // sampled; same-thread program order makes the overwrite safe)
            {
                const int nss = ss + ASTAGES;
                if (nss < SSTEPS) {
                    cpa16(asw + buf * 1024 + lane * 16,
                          tile + nss * OFF_SS);
                    cpa16(asw + buf * 1024 + 512 + lane * 16,
                          tile + nss * OFF_SS + OFF_HALF);
                }
            }
            asm volatile("cp.async.commit_group;");

            const int kpbase = (16 * ss + 4 * tig) * NSTRIDE;
#pragma unroll
            for (int m = 0; m < 2; m++) {
                const uint32_t a0 = (m == 0) ? va.x : va.z;
                const uint32_t a1 = (m == 0) ? vb.x : vb.z;
                const uint32_t a2 = (m == 0) ? va.y : va.w;
                const uint32_t a3 = (m == 0) ? vb.y : vb.w;
                const int r0 = kpbase + 2 * m * NSTRIDE;
#pragma unroll
                for (int t = 0; t < 3; t++) {
                    const int cn = 8 * t + gid;
                    const uint32_t b0 = Ts[r0 + cn];
                    const uint32_t b1 = Ts[r0 + NSTRIDE + cn];
                    asm volatile(
                        "mma.sync.aligned.m16n8k16.row.col.f32.f16.f16.f32 "
                        "{%0,%1,%2,%3},{%4,%5,%6,%7},{%8,%9},{%0,%1,%2,%3};"
                        : "+f"(acc[t][0]), "+f"(acc[t][1]),
                          "+f"(acc[t][2]), "+f"(acc[t][3])
                        : "r"(a0), "r"(a1), "r"(a2), "r"(a3),
                          "r"(b0), "r"(b1));
                }
            }
        }

        float* po = part + (size_t)slab * NROWS * F;
#pragma unroll
        for (int t = 0; t < 3; t++) {
            const int c = 8 * t + tig2;
            if (c < F) {
                const int r0 = m0 + gid;
                const int r1 = r0 + 8;
                *(float2*)(po + (size_t)r0 * F + c) =
                    make_float2(acc[t][0], acc[t][1]);
                *(float2*)(po + (size_t)r1 * F + c) =
                    make_float2(acc[t][2], acc[t][3]);
            }
        }
    }
}

// ---------------------------------------------------------------------------
// Fused reduce + small GEMM:
//   h[row][:] = relu( sum_s P[s][row][:] + b[:] ),  T[row][:] = h[row][:] @ W
// ---------------------------------------------------------------------------
__global__ void __launch_bounds__(256)
xwred_kernel(const float* __restrict__ P, const float* __restrict__ bias,
             const float* __restrict__ W, float* __restrict__ T)
{
    __shared__ float Ws[F * F];       // 20 x 20
    __shared__ float hs[8][F];
    const int tid  = threadIdx.x;
    const int warp = tid >> 5;
    const int lane = tid & 31;
    const int row  = blockIdx.x * 8 + warp;   // grid*8 == NROWS

    for (int i = tid; i < F * F; i += 256) Ws[i] = W[i];

    if (lane < F) {
        float s = 0.f;
#pragma unroll
        for (int sl = 0; sl < SPLIT; sl++)
            s += P[(size_t)sl * NROWS * F + (size_t)row * F + lane];
        hs[warp][lane] = fmaxf(s + bias[lane], 0.f);
    }
    __syncthreads();   // Ws staged + hs visible

    if (lane < F) {
        float t = 0.f;
#pragma unroll
        for (int k = 0; k < F; k++) t += hs[warp][k] * Ws[k * F + lane];
        T[(size_t)row * F + lane] = t;
    }
}

// ---------------------------------------------------------------------------
// Reduce partials (float4): out[i] = relu( sum_s part[s][i] + bias[i%20] )
// ---------------------------------------------------------------------------
__global__ void __launch_bounds__(256)
reduce_kernel(const float* __restrict__ part, const float* __restrict__ bias,
              float* __restrict__ out)
{
    const int i4 = (blockIdx.x * 256 + threadIdx.x) * 4;
    if (i4 < NROWS * F) {
        float4 s = make_float4(0.f, 0.f, 0.f, 0.f);
#pragma unroll
        for (int sl = 0; sl < SPLIT; sl++) {
            const float4 v = *(const float4*)(part + (size_t)sl * NROWS * F + i4);
            s.x += v.x; s.y += v.y; s.z += v.z; s.w += v.w;
        }
        float4 o;
        o.x = fmaxf(s.x + bias[(i4 + 0) % F], 0.f);
        o.y = fmaxf(s.y + bias[(i4 + 1) % F], 0.f);
        o.z = fmaxf(s.z + bias[(i4 + 2) % F], 0.f);
        o.w = fmaxf(s.w + bias[(i4 + 3) % F], 0.f);
        *(float4*)(out + i4) = o;
    }
}

// ---------------------------------------------------------------------------
// Small GEMM: T[N,20] = Hin[N,KK] @ W[KK,20].  Warp per row, lane = out col.
// ---------------------------------------------------------------------------
template <int KK>
__global__ void __launch_bounds__(256)
xw_kernel(const float* __restrict__ Hin, const float* __restrict__ W,
          float* __restrict__ T)
{
    __shared__ float Ws[KK * F];
    const int tid = threadIdx.x;
    for (int i = tid; i < KK * F; i += 256) Ws[i] = W[i];
    __syncthreads();

    const int warp = tid >> 5;
    const int lane = tid & 31;
    const int row  = blockIdx.x * 8 + warp;

    const float* h = Hin + (size_t)row * KK;
    if (lane < F) {
        float a0 = 0.f, a1 = 0.f, a2 = 0.f, a3 = 0.f;
#pragma unroll 4
        for (int k = 0; k < KK; k += 4) {
            a0 += h[k + 0] * Ws[(k + 0) * F + lane];
            a1 += h[k + 1] * Ws[(k + 1) * F + lane];
            a2 += h[k + 2] * Ws[(k + 2) * F + lane];
            a3 += h[k + 3] * Ws[(k + 3) * F + lane];
        }
        T[(size_t)row * F + lane] = (a0 + a1) + (a2 + a3);
    }
}

// ---------------------------------------------------------------------------
// Final (fused partial-reduce): out = relu( relu((sum_s P_s) @ W3 + b3) + x )
// ---------------------------------------------------------------------------
__global__ void __launch_bounds__(256)
final_kernel(const float* __restrict__ P, const float* __restrict__ W3,
             const float* __restrict__ b3, const float* __restrict__ x,
             float* __restrict__ out)
{
    __shared__ float Ws[F * D];
    __shared__ float ps[2 * F];
    const int tid = threadIdx.x;
    for (int i = tid; i < F * D; i += 256) Ws[i] = W3[i];

    const int row0 = blockIdx.x * 2;
    if (tid < 2 * F) {
        const int r = tid / F, c = tid % F;
        float s = 0.f;
#pragma unroll
        for (int sl = 0; sl < SPLIT; sl++)
            s += P[(size_t)sl * NROWS * F + (size_t)(row0 + r) * F + c];
        ps[tid] = s;
    }
    __syncthreads();

    const int r   = tid >> 7;
    const int col = tid & 127;

    float acc = b3[col];
#pragma unroll
    for (int k = 0; k < F; k++) acc += ps[r * F + k] * Ws[k * D + col];

    const float h = fmaxf(acc, 0.f);
    const size_t o = (size_t)(row0 + r) * D + col;
    out[o] = fmaxf(h + x[o], 0.f);
}

// ---------------------------------------------------------------------------
extern "C" void kernel_launch(void* const* d_in, const int* in_sizes, int n_in,
                              void* d_out, int out_size)
{
    const float* x   = (const float*)d_in[0];
    const float* adj = (const float*)d_in[1];
    const float* W1  = (const float*)d_in[2];
    const float* b1  = (const float*)d_in[3];
    const float* W2  = (const float*)d_in[4];
    const float* b2  = (const float*)d_in[5];
    const float* W3  = (const float*)d_in[6];
    const float* b3  = (const float*)d_in[7];
    float* out = (float*)d_out;

    float *T, *H, *P;
    cudaGetSymbolAddress((void**)&T, g_bufT);
    cudaGetSymbolAddress((void**)&H, g_bufH);
    cudaGetSymbolAddress((void**)&P, g_part);

    const dim3 SPMM_GRID(NSTRIP_GROUPS, SPLIT);          // 79 x 20, 256 thr
    const int  RED_GRID = (NROWS * F / 4 + 255) / 256;   // 196

    // T1 = x @ W1
    xw_kernel<D><<<NROWS / 8, 256>>>(x, W1, T);
    // P = partials of adj @ T1; also writes tiled fp16 adj copy
    spmm_fuse0_kernel<<<SPMM_GRID, 256>>>(adj, T, P);
    // T2 = relu(sum(P) + b1) @ W2   (fused reduce + xw)
    xwred_kernel<<<NROWS / 8, 256>>>(P, b1, W2, T);
    // P = partials of adj @ T2  (fp16 tiled adj)
    spmm_part_kernel<<<SPMM_GRID, 256>>>(T, P);
    // H2 = relu(sum(P) + b2)
    reduce_kernel<<<RED_GRID, 256>>>(P, b2, H);
    // P = partials of adj @ H2
    spmm_part_kernel<<<SPMM_GRID, 256>>>(H, P);
    // out = relu(relu(sum(P) @ W3 + b3) + x)
    final_kernel<<<NROWS / 2, 256>>>(P, W3, b3, x, out);
}

// round 15
// speedup vs baseline: 2.1206x; 1.0298x over previous
#include <cuda_runtime.h>
#include <cuda_fp16.h>
#include <cstdint>

// Problem constants
#define NROWS 10000
#define KDIM  10000
#define KH    10240     // fp16 adj padded cols (zeros beyond 10000)
#define F     20        // hidden width
#define D     128       // in/out width
#define NSTRIPS ((NROWS + 15) / 16)   // 625 (exact)

// K-split over the padded fp16 matrix: 20 slabs of 512 cols (32 | 512)
#define SPLIT  20
#define SLAB   512
#define SSTEPS (SLAB / 32)      // 16 supersteps (2 fp16 MMAs x 3 n-tiles each)
#define TILE_HALVES (16 * SLAB) // 8192 halves = 16 KB per (strip,slab) tile
#define STRIPS_PER_BLK 8
#define NSTRIP_GROUPS ((NSTRIPS + STRIPS_PER_BLK - 1) / STRIPS_PER_BLK)  // 79
#define ASTAGES 3               // cp.async A pipeline depth

// Intra-tile offsets IN HALVES:
#define OFF_TIG   8
#define OFF_GID   32
#define OFF_HALF  256
#define OFF_SS    512

// B smem: half2 words, [kpair 256][col stride 22] -> conflict-free LDS
#define NSTRIDE 22
#define TS_WORDS (256 * NSTRIDE + 32)

// Scratch (no allocations allowed)
__device__ float  g_bufT[NROWS * F];
__device__ float  g_bufH[NROWS * F];
__device__ float  g_part[SPLIT * NROWS * F];        // 16 MB partials
// Tiled fp16 adj: [strip 625][slab 20][ss 16][half 2][gid 8][tig 4][8 halves]
__device__ __half g_adjh[(size_t)NROWS * KH];       // 204.8 MB

__device__ __forceinline__ uint32_t pack_h2(float a, float b) {
    __half2 h = __floats2half2_rn(a, b);
    return *(uint32_t*)&h;
}
__device__ __forceinline__ uint32_t smem_u32(const void* p) {
    return (uint32_t)__cvta_generic_to_shared(p);
}
__device__ __forceinline__ void cpa16(uint32_t saddr, const void* gptr) {
    asm volatile("cp.async.cg.shared.global [%0], [%1], 16;"
                 :: "r"(saddr), "l"(gptr));
}

// Vectorized B staging: Ts[kp*22 + c] = half2(T[2kp][c], T[2kp+1][c]).
// Item (kp, c4): 2 coalesced float4 loads (rows 2kp, 2kp+1; 16-B aligned since
// 80*kp and 16*c4 are 16-B multiples), pack 4 half2, 2x uint2 STS (8-B aligned).
// 1280 items / 256 threads = 5 items each; consecutive tid -> sequential gmem.
__device__ __forceinline__ void stage_B(const float* __restrict__ src,
                                        uint32_t* __restrict__ Ts, int tid)
{
#pragma unroll
    for (int it = 0; it < 5; ++it) {
        const int i  = it * 256 + tid;      // 0..1279
        const int kp = i / 5;
        const int c4 = i % 5;
        const float4 f0 = *(const float4*)(src + kp * 40 + 4 * c4);
        const float4 f1 = *(const float4*)(src + kp * 40 + 20 + 4 * c4);
        uint2 lo, hi;
        lo.x = pack_h2(f0.x, f1.x); lo.y = pack_h2(f0.y, f1.y);
        hi.x = pack_h2(f0.z, f1.z); hi.y = pack_h2(f0.w, f1.w);
        uint32_t* dst = &Ts[kp * NSTRIDE + 4 * c4];
        *(uint2*)(dst)     = lo;
        *(uint2*)(dst + 2) = hi;
    }
}

// ---------------------------------------------------------------------------
// PASS 0 (fused convert + GEMM): reads fp32 adj, writes tiled fp16 copy,
// computes part[slab][N,20] = adj[:,slab] @ T[slab,20] with fp16 m16n8k16.
// ---------------------------------------------------------------------------
__global__ void __launch_bounds__(256, 3)
spmm_fuse0_kernel(const float* __restrict__ adj,
                  const float* __restrict__ T,
                  float* __restrict__ part)
{
    __shared__ uint32_t Ts[TS_WORDS];   // half2 words

    const int tid  = threadIdx.x;
    const int warp = tid >> 5;
    const int lane = tid & 31;
    const int gid  = lane >> 2;
    const int tig  = lane & 3;
    const int tig2 = 2 * tig;

    if (tid < 32) Ts[256 * NSTRIDE + tid] = 0;

    const int strip  = blockIdx.x * STRIPS_PER_BLK + warp;
    const bool active = (strip < NSTRIPS);
    const int m0   = strip * 16;
    const int slab = blockIdx.y;
    const int cbase = slab * SLAB;       // fp32 col base of this slab

    const float* a_row0 = adj + (size_t)(active ? (m0 + gid) : 0) * KDIM;
    const float* a_row1 = a_row0 + (size_t)8 * KDIM;
    __half* tile_w = g_adjh
        + ((size_t)(active ? strip : 0) * SPLIT + slab) * TILE_HALVES
        + lane * OFF_TIG;               // lane-linear write base

    // stage B slab (vectorized)
    stage_B(T + (size_t)slab * SLAB * F, Ts, tid);

    float acc[3][4];
#pragma unroll
    for (int t = 0; t < 3; t++)
#pragma unroll
        for (int j = 0; j < 4; j++) acc[t][j] = 0.0f;

    // fp32 A double-buffer ring (2 supersteps deep)
    float4 r0a[2], r0b[2], r1a[2], r1b[2];
    if (active) {
#pragma unroll
        for (int p = 0; p < 2; p++) {
            const int gc = cbase + 32 * p + 8 * tig;
            const bool v = (gc < KDIM);   // 8-col group wholly valid or not
            r0a[p] = v ? *(const float4*)(a_row0 + gc)     : make_float4(0,0,0,0);
            r0b[p] = v ? *(const float4*)(a_row0 + gc + 4) : make_float4(0,0,0,0);
            r1a[p] = v ? *(const float4*)(a_row1 + gc)     : make_float4(0,0,0,0);
            r1b[p] = v ? *(const float4*)(a_row1 + gc + 4) : make_float4(0,0,0,0);
        }
    }

    __syncthreads();

    if (active) {
#pragma unroll 2
        for (int ss = 0; ss < SSTEPS; ++ss) {
            const int slot = ss & 1;
            const float4 f0a = r0a[slot], f0b = r0b[slot];
            const float4 f1a = r1a[slot], f1b = r1b[slot];

            // prefetch superstep ss+2
            {
                const int nss = ss + 2;
                if (nss < SSTEPS) {
                    const int gc = cbase + 32 * nss + 8 * tig;
                    const bool v = (gc < KDIM);
                    r0a[slot] = v ? *(const float4*)(a_row0 + gc)     : make_float4(0,0,0,0);
                    r0b[slot] = v ? *(const float4*)(a_row0 + gc + 4) : make_float4(0,0,0,0);
                    r1a[slot] = v ? *(const float4*)(a_row1 + gc)     : make_float4(0,0,0,0);
                    r1b[slot] = v ? *(const float4*)(a_row1 + gc + 4) : make_float4(0,0,0,0);
                }
            }

            // convert: va/vb match the tiled layout's register image exactly
            uint4 va, vb;
            va.x = pack_h2(f0a.x, f0a.y); va.y = pack_h2(f0a.z, f0a.w);
            va.z = pack_h2(f0b.x, f0b.y); va.w = pack_h2(f0b.z, f0b.w);
            vb.x = pack_h2(f1a.x, f1a.y); vb.y = pack_h2(f1a.z, f1a.w);
            vb.z = pack_h2(f1b.x, f1b.y); vb.w = pack_h2(f1b.z, f1b.w);

            // tiled fp16 write (warp: 2 x 512 B contiguous, lane-linear)
            *(uint4*)(tile_w + ss * OFF_SS)            = va;
            *(uint4*)(tile_w + ss * OFF_SS + OFF_HALF) = vb;

            const int kpbase = (16 * ss + 4 * tig) * NSTRIDE;
#pragma unroll
            for (int m = 0; m < 2; m++) {
                const uint32_t a0 = (m == 0) ? va.x : va.z;
                const uint32_t a1 = (m == 0) ? vb.x : vb.z;
                const uint32_t a2 = (m == 0) ? va.y : va.w;
                const uint32_t a3 = (m == 0) ? vb.y : vb.w;
                const int r0 = kpbase + 2 * m * NSTRIDE;
#pragma unroll
                for (int t = 0; t < 3; t++) {
                    const int cn = 8 * t + gid;
                    const uint32_t b0 = Ts[r0 + cn];
                    const uint32_t b1 = Ts[r0 + NSTRIDE + cn];
                    asm volatile(
                        "mma.sync.aligned.m16n8k16.row.col.f32.f16.f16.f32 "
                        "{%0,%1,%2,%3},{%4,%5,%6,%7},{%8,%9},{%0,%1,%2,%3};"
                        : "+f"(acc[t][0]), "+f"(acc[t][1]),
                          "+f"(acc[t][2]), "+f"(acc[t][3])
                        : "r"(a0), "r"(a1), "r"(a2), "r"(a3),
                          "r"(b0), "r"(b1));
                }
            }
        }

        float* po = part + (size_t)slab * NROWS * F;
#pragma unroll
        for (int t = 0; t < 3; t++) {
            const int c = 8 * t + tig2;
            if (c < F) {
                const int r0 = m0 + gid;
                const int r1 = r0 + 8;
                *(float2*)(po + (size_t)r0 * F + c) =
                    make_float2(acc[t][0], acc[t][1]);
                *(float2*)(po + (size_t)r1 * F + c) =
                    make_float2(acc[t][2], acc[t][3]);
            }
        }
    }
}

// ---------------------------------------------------------------------------
// Big GEMM partial (fp16 m16n8k16, tiled adj): passes 2 and 3.
// A path: per-warp 3-stage cp.async pipeline into smem; sync is
// cp.async.wait_group only (each lane copies exactly the 16 B it consumes).
// ---------------------------------------------------------------------------
__global__ void __launch_bounds__(256, 4)
spmm_part_kernel(const float* __restrict__ T,
                 float* __restrict__ part)
{
    __shared__ uint32_t Ts[TS_WORDS];
    __shared__ __align__(16) __half As[STRIPS_PER_BLK][ASTAGES][512]; // 24 KB

    const int tid  = threadIdx.x;
    const int warp = tid >> 5;
    const int lane = tid & 31;
    const int gid  = lane >> 2;
    const int tig  = lane & 3;
    const int tig2 = 2 * tig;

    if (tid < 32) Ts[256 * NSTRIDE + tid] = 0;

    const int strip  = blockIdx.x * STRIPS_PER_BLK + warp;
    const bool active = (strip < NSTRIPS);
    const int strip_c = active ? strip : (NSTRIPS - 1);
    const int m0   = strip * 16;
    const int slab = blockIdx.y;

    const __half* tile = g_adjh
        + ((size_t)strip_c * SPLIT + slab) * TILE_HALVES
        + lane * OFF_TIG;                     // lane-linear global base

    const uint32_t asw = smem_u32(&As[warp][0][0]);  // warp's stage base

    // prologue: fill all ASTAGES stages (A-stream in flight during B staging)
#pragma unroll
    for (int p = 0; p < ASTAGES; p++) {
        cpa16(asw + p * 1024 + lane * 16,       tile + p * OFF_SS);
        cpa16(asw + p * 1024 + 512 + lane * 16, tile + p * OFF_SS + OFF_HALF);
        asm volatile("cp.async.commit_group;");
    }

    // stage B slab (vectorized)
    stage_B(T + (size_t)slab * SLAB * F, Ts, tid);

    float acc[3][4];
#pragma unroll
    for (int t = 0; t < 3; t++)
#pragma unroll
        for (int j = 0; j < 4; j++) acc[t][j] = 0.0f;

    __syncthreads();   // B staging visible to all warps

    if (active) {
#pragma unroll
        for (int ss = 0; ss < SSTEPS; ++ss) {
            const int buf = ss % ASTAGES;      // compile-time (full unroll)

            // stage ss is complete once <= ASTAGES-1 groups remain pending
            asm volatile("cp.async.wait_group %0;" :: "n"(ASTAGES - 1));

            // consume own 16-B slots (written by this same lane)
            const uint4 va = *(const uint4*)&As[warp][buf][lane * 8];
            const uint4 vb = *(const uint4*)&As[warp][buf][256 + lane * 8];

            // refill this buffer with stage ss+ASTAGES (same-thread program
            // order makes the overwrite safe)
            {
                const int nss = ss + ASTAGES;
                if (nss < SSTEPS) {
                    cpa16(asw + buf * 1024 + lane * 16,
                          tile + nss * OFF_SS);
                    cpa16(asw + buf * 1024 + 512 + lane * 16,
                          tile + nss * OFF_SS + OFF_HALF);
                }
            }
            asm volatile("cp.async.commit_group;");

            const int kpbase = (16 * ss + 4 * tig) * NSTRIDE;
#pragma unroll
            for (int m = 0; m < 2; m++) {
                const uint32_t a0 = (m == 0) ? va.x : va.z;
                const uint32_t a1 = (m == 0) ? vb.x : vb.z;
                const uint32_t a2 = (m == 0) ? va.y : va.w;
                const uint32_t a3 = (m == 0) ? vb.y : vb.w;
                const int r0 = kpbase + 2 * m * NSTRIDE;
#pragma unroll
                for (int t = 0; t < 3; t++) {
                    const int cn = 8 * t + gid;
                    const uint32_t b0 = Ts[r0 + cn];
                    const uint32_t b1 = Ts[r0 + NSTRIDE + cn];
                    asm volatile(
                        "mma.sync.aligned.m16n8k16.row.col.f32.f16.f16.f32 "
                        "{%0,%1,%2,%3},{%4,%5,%6,%7},{%8,%9},{%0,%1,%2,%3};"
                        : "+f"(acc[t][0]), "+f"(acc[t][1]),
                          "+f"(acc[t][2]), "+f"(acc[t][3])
                        : "r"(a0), "r"(a1), "r"(a2), "r"(a3),
                          "r"(b0), "r"(b1));
                }
            }
        }

        float* po = part + (size_t)slab * NROWS * F;
#pragma unroll
        for (int t = 0; t < 3; t++) {
            const int c = 8 * t + tig2;
            if (c < F) {
                const int r0 = m0 + gid;
                const int r1 = r0 + 8;
                *(float2*)(po + (size_t)r0 * F + c) =
                    make_float2(acc[t][0], acc[t][1]);
                *(float2*)(po + (size_t)r1 * F + c) =
                    make_float2(acc[t][2], acc[t][3]);
            }
        }
    }
}

// ---------------------------------------------------------------------------
// Fused reduce + small GEMM:
//   h[row][:] = relu( sum_s P[s][row][:] + b[:] ),  T[row][:] = h[row][:] @ W
// ---------------------------------------------------------------------------
__global__ void __launch_bounds__(256)
xwred_kernel(const float* __restrict__ P, const float* __restrict__ bias,
             const float* __restrict__ W, float* __restrict__ T)
{
    __shared__ float Ws[F * F];       // 20 x 20
    __shared__ float hs[8][F];
    const int tid  = threadIdx.x;
    const int warp = tid >> 5;
    const int lane = tid & 31;
    const int row  = blockIdx.x * 8 + warp;   // grid*8 == NROWS

    for (int i = tid; i < F * F; i += 256) Ws[i] = W[i];

    if (lane < F) {
        float s = 0.f;
#pragma unroll
        for (int sl = 0; sl < SPLIT; sl++)
            s += P[(size_t)sl * NROWS * F + (size_t)row * F + lane];
        hs[warp][lane] = fmaxf(s + bias[lane], 0.f);
    }
    __syncthreads();   // Ws staged + hs visible

    if (lane < F) {
        float t = 0.f;
#pragma unroll
        for (int k = 0; k < F; k++) t += hs[warp][k] * Ws[k * F + lane];
        T[(size_t)row * F + lane] = t;
    }
}

// ---------------------------------------------------------------------------
// Reduce partials (float4): out[i] = relu( sum_s part[s][i] + bias[i%20] )
// ---------------------------------------------------------------------------
__global__ void __launch_bounds__(256)
reduce_kernel(const float* __restrict__ part, const float* __restrict__ bias,
              float* __restrict__ out)
{
    const int i4 = (blockIdx.x * 256 + threadIdx.x) * 4;
    if (i4 < NROWS * F) {
        float4 s = make_float4(0.f, 0.f, 0.f, 0.f);
#pragma unroll
        for (int sl = 0; sl < SPLIT; sl++) {
            const float4 v = *(const float4*)(part + (size_t)sl * NROWS * F + i4);
            s.x += v.x; s.y += v.y; s.z += v.z; s.w += v.w;
        }
        float4 o;
        o.x = fmaxf(s.x + bias[(i4 + 0) % F], 0.f);
        o.y = fmaxf(s.y + bias[(i4 + 1) % F], 0.f);
        o.z = fmaxf(s.z + bias[(i4 + 2) % F], 0.f);
        o.w = fmaxf(s.w + bias[(i4 + 3) % F], 0.f);
        *(float4*)(out + i4) = o;
    }
}

// ---------------------------------------------------------------------------
// Small GEMM: T[N,20] = Hin[N,KK] @ W[KK,20].  Warp per row, lane = out col.
// ---------------------------------------------------------------------------
template <int KK>
__global__ void __launch_bounds__(256)
xw_kernel(const float* __restrict__ Hin, const float* __restrict__ W,
          float* __restrict__ T)
{
    __shared__ float Ws[KK * F];
    const int tid = threadIdx.x;
    for (int i = tid; i < KK * F; i += 256) Ws[i] = W[i];
    __syncthreads();

    const int warp = tid >> 5;
    const int lane = tid & 31;
    const int row  = blockIdx.x * 8 + warp;

    const float* h = Hin + (size_t)row * KK;
    if (lane < F) {
        float a0 = 0.f, a1 = 0.f, a2 = 0.f, a3 = 0.f;
#pragma unroll 4
        for (int k = 0; k < KK; k += 4) {
            a0 += h[k + 0] * Ws[(k + 0) * F + lane];
            a1 += h[k + 1] * Ws[(k + 1) * F + lane];
            a2 += h[k + 2] * Ws[(k + 2) * F + lane];
            a3 += h[k + 3] * Ws[(k + 3) * F + lane];
        }
        T[(size_t)row * F + lane] = (a0 + a1) + (a2 + a3);
    }
}

// ---------------------------------------------------------------------------
// Final (fused partial-reduce): out = relu( relu((sum_s P_s) @ W3 + b3) + x )
// ---------------------------------------------------------------------------
__global__ void __launch_bounds__(256)
final_kernel(const float* __restrict__ P, const float* __restrict__ W3,
             const float* __restrict__ b3, const float* __restrict__ x,
             float* __restrict__ out)
{
    __shared__ float Ws[F * D];
    __shared__ float ps[2 * F];
    const int tid = threadIdx.x;
    for (int i = tid; i < F * D; i += 256) Ws[i] = W3[i];

    const int row0 = blockIdx.x * 2;
    if (tid < 2 * F) {
        const int r = tid / F, c = tid % F;
        float s = 0.f;
#pragma unroll
        for (int sl = 0; sl < SPLIT; sl++)
            s += P[(size_t)sl * NROWS * F + (size_t)(row0 + r) * F + c];
        ps[tid] = s;
    }
    __syncthreads();

    const int r   = tid >> 7;
    const int col = tid & 127;

    float acc = b3[col];
#pragma unroll
    for (int k = 0; k < F; k++) acc += ps[r * F + k] * Ws[k * D + col];

    const float h = fmaxf(acc, 0.f);
    const size_t o = (size_t)(row0 + r) * D + col;
    out[o] = fmaxf(h + x[o], 0.f);
}

// ---------------------------------------------------------------------------
extern "C" void kernel_launch(void* const* d_in, const int* in_sizes, int n_in,
                              void* d_out, int out_size)
{
    const float* x   = (const float*)d_in[0];
    const float* adj = (const float*)d_in[1];
    const float* W1  = (const float*)d_in[2];
    const float* b1  = (const float*)d_in[3];
    const float* W2  = (const float*)d_in[4];
    const float* b2  = (const float*)d_in[5];
    const float* W3  = (const float*)d_in[6];
    const float* b3  = (const float*)d_in[7];
    float* out = (float*)d_out;

    float *T, *H, *P;
    cudaGetSymbolAddress((void**)&T, g_bufT);
    cudaGetSymbolAddress((void**)&H, g_bufH);
    cudaGetSymbolAddress((void**)&P, g_part);

    const dim3 SPMM_GRID(NSTRIP_GROUPS, SPLIT);          // 79 x 20, 256 thr
    const int  RED_GRID = (NROWS * F / 4 + 255) / 256;   // 196

    // T1 = x @ W1
    xw_kernel<D><<<NROWS / 8, 256>>>(x, W1, T);
    // P = partials of adj @ T1; also writes tiled fp16 adj copy
    spmm_fuse0_kernel<<<SPMM_GRID, 256>>>(adj, T, P);
    // T2 = relu(sum(P) + b1) @ W2   (fused reduce + xw)
    xwred_kernel<<<NROWS / 8, 256>>>(P, b1, W2, T);
    // P = partials of adj @ T2  (fp16 tiled adj)
    spmm_part_kernel<<<SPMM_GRID, 256>>>(T, P);
    // H2 = relu(sum(P) + b2)
    reduce_kernel<<<RED_GRID, 256>>>(P, b2, H);
    // P = partials of adj @ H2
    spmm_part_kernel<<<SPMM_GRID, 256>>>(H, P);
    // out = relu(relu(sum(P) @ W3 + b3) + x)
    final_kernel<<<NROWS / 2, 256>>>(P, W3, b3, x, out);
}